// round 1
// baseline (speedup 1.0000x reference)
#include <cuda_runtime.h>
#include <math.h>
#include <stdint.h>

#define NB   2
#define SEQ  2048
#define EMB  1024
#define NH   16
#define NKV  8
#define HD   64
#define MROWS (NB*SEQ)   // 4096

// ---------------- scratch (no allocations allowed) ----------------
__device__ float g_q[(size_t)MROWS * NH * HD];    // 16 MB
__device__ float g_k[(size_t)MROWS * NKV * HD];   // 8 MB
__device__ float g_v[(size_t)MROWS * NKV * HD];   // 8 MB
__device__ float g_attn[(size_t)MROWS * NH * HD]; // 16 MB

// =====================================================================
// GEMM: C[M,N] = A[M,K] @ B[N,K]^T (+ bias[N]).  A,B row-major.
// BM=BN=128, BK=16, 256 threads, 8x8 register tile per thread.
// =====================================================================
__global__ __launch_bounds__(256, 2)
void gemm_nt(const float* __restrict__ A, const float* __restrict__ B,
             const float* __restrict__ bias, float* __restrict__ C,
             int M, int N, int K)
{
    __shared__ float As[16][132];   // [k][m], padded
    __shared__ float Bs[16][132];   // [k][n], padded

    const int tid = threadIdx.x;
    const int tx = tid & 15;
    const int ty = tid >> 4;
    const int m0 = blockIdx.y * 128;
    const int n0 = blockIdx.x * 128;

    float acc[8][8];
#pragma unroll
    for (int i = 0; i < 8; i++)
#pragma unroll
        for (int j = 0; j < 8; j++) acc[i][j] = 0.f;

    for (int k0 = 0; k0 < K; k0 += 16) {
#pragma unroll
        for (int p = 0; p < 2; p++) {
            int f4  = tid + p * 256;      // 0..511
            int row = f4 >> 2;            // 0..127
            int c4  = (f4 & 3) * 4;       // 0,4,8,12
            float4 a = *(const float4*)(A + (size_t)(m0 + row) * K + k0 + c4);
            As[c4 + 0][row] = a.x; As[c4 + 1][row] = a.y;
            As[c4 + 2][row] = a.z; As[c4 + 3][row] = a.w;
            float4 b = *(const float4*)(B + (size_t)(n0 + row) * K + k0 + c4);
            Bs[c4 + 0][row] = b.x; Bs[c4 + 1][row] = b.y;
            Bs[c4 + 2][row] = b.z; Bs[c4 + 3][row] = b.w;
        }
        __syncthreads();

#pragma unroll
        for (int kk = 0; kk < 16; kk++) {
            float a[8], b[8];
            *(float4*)&a[0] = *(const float4*)&As[kk][ty * 8];
            *(float4*)&a[4] = *(const float4*)&As[kk][ty * 8 + 4];
            *(float4*)&b[0] = *(const float4*)&Bs[kk][tx * 8];
            *(float4*)&b[4] = *(const float4*)&Bs[kk][tx * 8 + 4];
#pragma unroll
            for (int i = 0; i < 8; i++)
#pragma unroll
                for (int j = 0; j < 8; j++)
                    acc[i][j] = fmaf(a[i], b[j], acc[i][j]);
        }
        __syncthreads();
    }

    float bb[8];
#pragma unroll
    for (int j = 0; j < 8; j++) bb[j] = bias ? bias[n0 + tx * 8 + j] : 0.f;

#pragma unroll
    for (int i = 0; i < 8; i++) {
        float4 o0, o1;
        o0.x = acc[i][0] + bb[0]; o0.y = acc[i][1] + bb[1];
        o0.z = acc[i][2] + bb[2]; o0.w = acc[i][3] + bb[3];
        o1.x = acc[i][4] + bb[4]; o1.y = acc[i][5] + bb[5];
        o1.z = acc[i][6] + bb[6]; o1.w = acc[i][7] + bb[7];
        float* cp = C + (size_t)(m0 + ty * 8 + i) * N + n0 + tx * 8;
        *(float4*)cp       = o0;
        *(float4*)(cp + 4) = o1;
    }
}

// =====================================================================
// Flash attention with symmetric ALiBi, GQA (kv head = h/2).
// BQ=64 queries per block, BK=64 keys per tile, D=64.
// 256 threads: (ty,tx) 16x16, 4x4 register tiles.
// Q,K stored d-major [dd][col] (stride 68) with XOR swizzle on col.
// V stored k-major [k][d] (stride 68). P stored [q][k] (stride 68).
// =====================================================================
#define LDST 68   // padded row stride in floats

__global__ __launch_bounds__(256, 2)
void flash_attn()
{
    extern __shared__ float sm[];
    float* Qt = sm;                // [64][68] d-major, swizzled
    float* Kt = Qt + 64 * LDST;    // [64][68] d-major, swizzled
    float* Vs = Kt + 64 * LDST;    // [64][68] k-major
    float* Ps = Vs + 64 * LDST;    // [64][68] q-major

    const int tid = threadIdx.x;
    const int tx = tid & 15;
    const int ty = tid >> 4;
    const int qb = blockIdx.x;
    const int h  = blockIdx.y;
    const int n  = blockIdx.z;
    const int q0 = qb * 64;
    const int kvh = h >> 1;
    const float slope = exp2f(-(float)(h + 1));   // ALIBI_ALPHA=1, START_I=0

    // ---- load Q tile: transpose to [dd][q], swizzled col = q ^ (d4*4) ----
#pragma unroll
    for (int p = 0; p < 4; p++) {
        int f4 = tid + p * 256;        // 0..1023
        int qi = f4 >> 4;              // 0..63
        int d4 = f4 & 15;              // 0..15
        float4 a = *(const float4*)(g_q + (size_t)(n * SEQ + q0 + qi) * (NH * HD)
                                        + h * HD + d4 * 4);
        int sc = qi ^ (d4 * 4);
        Qt[(d4 * 4 + 0) * LDST + sc] = a.x;
        Qt[(d4 * 4 + 1) * LDST + sc] = a.y;
        Qt[(d4 * 4 + 2) * LDST + sc] = a.z;
        Qt[(d4 * 4 + 3) * LDST + sc] = a.w;
    }

    float m_run[4], l_run[4], acc[4][4];
#pragma unroll
    for (int i = 0; i < 4; i++) {
        m_run[i] = -INFINITY; l_run[i] = 0.f;
#pragma unroll
        for (int j = 0; j < 4; j++) acc[i][j] = 0.f;
    }

    const float tq0 = (float)(q0 + ty * 4);

    for (int kb = 0; kb < SEQ / 64; kb++) {
        __syncthreads();   // previous AV done before overwriting Kt/Vs

        // ---- load K (transposed+swizzled) and V (k-major) tiles ----
#pragma unroll
        for (int p = 0; p < 4; p++) {
            int f4 = tid + p * 256;
            int ki = f4 >> 4;
            int d4 = f4 & 15;
            size_t gk = (size_t)(n * SEQ + kb * 64 + ki) * (NKV * HD) + kvh * HD + d4 * 4;
            float4 a = *(const float4*)(g_k + gk);
            int sc = ki ^ (d4 * 4);
            Kt[(d4 * 4 + 0) * LDST + sc] = a.x;
            Kt[(d4 * 4 + 1) * LDST + sc] = a.y;
            Kt[(d4 * 4 + 2) * LDST + sc] = a.z;
            Kt[(d4 * 4 + 3) * LDST + sc] = a.w;
            float4 b = *(const float4*)(g_v + gk);
            *(float4*)&Vs[ki * LDST + d4 * 4] = b;
        }
        __syncthreads();

        // ---- S = Q @ K^T ----
        float s[4][4];
#pragma unroll
        for (int i = 0; i < 4; i++)
#pragma unroll
            for (int j = 0; j < 4; j++) s[i][j] = 0.f;

#pragma unroll 8
        for (int dd = 0; dd < 64; dd++) {
            int X = dd & ~3;           // (dd>>2)*4
            float4 qv = *(const float4*)&Qt[dd * LDST + ((ty * 4) ^ X)];
            float4 kv = *(const float4*)&Kt[dd * LDST + ((tx * 4) ^ X)];
            float qa[4] = {qv.x, qv.y, qv.z, qv.w};
            float ka[4] = {kv.x, kv.y, kv.z, kv.w};
#pragma unroll
            for (int i = 0; i < 4; i++)
#pragma unroll
                for (int j = 0; j < 4; j++)
                    s[i][j] = fmaf(qa[i], ka[j], s[i][j]);
        }

        // ---- ALiBi bias + scale: (qk - dist*slope) * 1/sqrt(64) ----
        const float tk0 = (float)(kb * 64 + tx * 4);
#pragma unroll
        for (int i = 0; i < 4; i++)
#pragma unroll
            for (int j = 0; j < 4; j++) {
                float dist = fabsf((tq0 + i) - (tk0 + j));
                s[i][j] = (s[i][j] - dist * slope) * 0.125f;
            }

        // ---- online softmax ----
#pragma unroll
        for (int i = 0; i < 4; i++) {
            float mt = fmaxf(fmaxf(s[i][0], s[i][1]), fmaxf(s[i][2], s[i][3]));
#pragma unroll
            for (int msk = 1; msk < 16; msk <<= 1)
                mt = fmaxf(mt, __shfl_xor_sync(0xffffffffu, mt, msk));
            float mnew = fmaxf(m_run[i], mt);
            float corr = __expf(m_run[i] - mnew);   // 0 when m_run = -inf
            m_run[i] = mnew;
            float rs = 0.f;
#pragma unroll
            for (int j = 0; j < 4; j++) {
                float pv = __expf(s[i][j] - mnew);
                s[i][j] = pv;
                rs += pv;
            }
#pragma unroll
            for (int msk = 1; msk < 16; msk <<= 1)
                rs += __shfl_xor_sync(0xffffffffu, rs, msk);
            l_run[i] = l_run[i] * corr + rs;
#pragma unroll
            for (int j = 0; j < 4; j++) acc[i][j] *= corr;
            // store P row chunk (float4, conflict-free: consecutive tx)
            float4 pr; pr.x = s[i][0]; pr.y = s[i][1]; pr.z = s[i][2]; pr.w = s[i][3];
            *(float4*)&Ps[(ty * 4 + i) * LDST + tx * 4] = pr;
        }
        __syncthreads();

        // ---- O += P @ V ----
#pragma unroll 4
        for (int k4 = 0; k4 < 16; k4++) {
            float pv[4][4];
#pragma unroll
            for (int i = 0; i < 4; i++)
                *(float4*)pv[i] = *(const float4*)&Ps[(ty * 4 + i) * LDST + k4 * 4];
#pragma unroll
            for (int c = 0; c < 4; c++) {
                float4 vv = *(const float4*)&Vs[(k4 * 4 + c) * LDST + tx * 4];
                float va[4] = {vv.x, vv.y, vv.z, vv.w};
#pragma unroll
                for (int i = 0; i < 4; i++)
#pragma unroll
                    for (int j = 0; j < 4; j++)
                        acc[i][j] = fmaf(pv[i][c], va[j], acc[i][j]);
            }
        }
    }

    // ---- normalize + write ----
#pragma unroll
    for (int i = 0; i < 4; i++) {
        float inv = 1.f / l_run[i];
        float4 o;
        o.x = acc[i][0] * inv; o.y = acc[i][1] * inv;
        o.z = acc[i][2] * inv; o.w = acc[i][3] * inv;
        *(float4*)(g_attn + (size_t)(n * SEQ + q0 + ty * 4 + i) * (NH * HD)
                          + h * HD + tx * 4) = o;
    }
}

// =====================================================================
// launch
// =====================================================================
extern "C" void kernel_launch(void* const* d_in, const int* in_sizes, int n_in,
                              void* d_out, int out_size)
{
    const float* x  = (const float*)d_in[0];
    const float* Wq = (const float*)d_in[1];
    const float* Wk = (const float*)d_in[2];
    const float* Wv = (const float*)d_in[3];
    const float* Wo = (const float*)d_in[4];
    const float* bo = (const float*)d_in[5];
    float* out = (float*)d_out;

    float *qp, *kp, *vp, *ap;
    cudaGetSymbolAddress((void**)&qp, g_q);
    cudaGetSymbolAddress((void**)&kp, g_k);
    cudaGetSymbolAddress((void**)&vp, g_v);
    cudaGetSymbolAddress((void**)&ap, g_attn);

    // QKV projections
    gemm_nt<<<dim3((NH * HD) / 128, MROWS / 128), 256>>>(x, Wq, nullptr, qp,
                                                         MROWS, NH * HD, EMB);
    gemm_nt<<<dim3((NKV * HD) / 128, MROWS / 128), 256>>>(x, Wk, nullptr, kp,
                                                          MROWS, NKV * HD, EMB);
    gemm_nt<<<dim3((NKV * HD) / 128, MROWS / 128), 256>>>(x, Wv, nullptr, vp,
                                                          MROWS, NKV * HD, EMB);

    // attention
    int smem = 4 * 64 * LDST * (int)sizeof(float);   // 69632 B
    cudaFuncSetAttribute(flash_attn, cudaFuncAttributeMaxDynamicSharedMemorySize, smem);
    flash_attn<<<dim3(SEQ / 64, NH, NB), 256, smem>>>();

    // output projection + bias
    gemm_nt<<<dim3(EMB / 128, MROWS / 128), 256>>>(ap, Wo, bo, out,
                                                   MROWS, EMB, EMB);
}

// round 3
// speedup vs baseline: 1.3834x; 1.3834x over previous
#include <cuda_runtime.h>
#include <math.h>
#include <stdint.h>

#define NB   2
#define SEQ  2048
#define EMB  1024
#define NH   16
#define NKV  8
#define HD   64
#define MROWS (NB*SEQ)   // 4096

// ---------------- scratch (no allocations allowed) ----------------
__device__ float g_q[(size_t)MROWS * NH * HD];    // 16 MB
__device__ float g_k[(size_t)MROWS * NKV * HD];   // 8 MB
__device__ float g_v[(size_t)MROWS * NKV * HD];   // 8 MB
__device__ float g_attn[(size_t)MROWS * NH * HD]; // 16 MB

// =====================================================================
// helpers
// =====================================================================
__device__ __forceinline__ uint32_t f2tf(float f) {
    uint32_t u;
    asm("cvt.rna.tf32.f32 %0, %1;" : "=r"(u) : "f"(f));
    return u;
}
__device__ __forceinline__ void mma_tf32(float* d, const uint32_t* a, const uint32_t* b) {
    asm volatile(
        "mma.sync.aligned.m16n8k8.row.col.f32.tf32.tf32.f32 "
        "{%0,%1,%2,%3}, {%4,%5,%6,%7}, {%8,%9}, {%0,%1,%2,%3};"
        : "+f"(d[0]), "+f"(d[1]), "+f"(d[2]), "+f"(d[3])
        : "r"(a[0]), "r"(a[1]), "r"(a[2]), "r"(a[3]), "r"(b[0]), "r"(b[1]));
}

// =====================================================================
// mma.sync tf32 GEMM: C[M,N] = A[M,K] @ B[N,K]^T (+ bias[N])
// Block tile 128x128, K-chunk 32. 256 threads = 8 warps (2x4),
// warp tile 64x32 = 4x4 tiles of m16n8k8.
// SMEM stride 36 words -> conflict-free fragment loads.
// Register-prefetch pipeline over K chunks.
// =====================================================================
#define LT 36

__global__ __launch_bounds__(256)
void gemm_mma(const float* __restrict__ A, const float* __restrict__ B,
              const float* __restrict__ bias, float* __restrict__ C,
              int M, int N, int K)
{
    __shared__ uint32_t As[128][LT];
    __shared__ uint32_t Bs[128][LT];

    const int tid  = threadIdx.x;
    const int lane = tid & 31;
    const int wid  = tid >> 5;
    const int wm   = wid >> 2;        // 0..1
    const int wn   = wid & 3;         // 0..3
    const int m0   = blockIdx.y * 128;
    const int n0   = blockIdx.x * 128;

    const int srow = tid >> 3;        // 0..31 (base)
    const int sc4  = (tid & 7) * 4;   // 0..28

    float acc[4][4][4];
#pragma unroll
    for (int mt = 0; mt < 4; mt++)
#pragma unroll
        for (int nt = 0; nt < 4; nt++)
#pragma unroll
            for (int i = 0; i < 4; i++) acc[mt][nt][i] = 0.f;

    float4 ra[4], rb[4];

    // prologue: load chunk 0 into regs, stage to SMEM
#pragma unroll
    for (int p = 0; p < 4; p++) {
        int row = srow + p * 32;
        ra[p] = *(const float4*)(A + (size_t)(m0 + row) * K + sc4);
        rb[p] = *(const float4*)(B + (size_t)(n0 + row) * K + sc4);
    }
#pragma unroll
    for (int p = 0; p < 4; p++) {
        int row = srow + p * 32;
        uint4 ta = { f2tf(ra[p].x), f2tf(ra[p].y), f2tf(ra[p].z), f2tf(ra[p].w) };
        *(uint4*)&As[row][sc4] = ta;
        uint4 tb = { f2tf(rb[p].x), f2tf(rb[p].y), f2tf(rb[p].z), f2tf(rb[p].w) };
        *(uint4*)&Bs[row][sc4] = tb;
    }
    __syncthreads();

    const int NC = K / 32;
    const int fr = lane >> 2;     // 0..7
    const int fc = lane & 3;      // 0..3

    for (int ch = 0; ch < NC; ch++) {
        // prefetch next chunk into registers (hidden behind mma work)
        if (ch + 1 < NC) {
            int k0 = (ch + 1) * 32;
#pragma unroll
            for (int p = 0; p < 4; p++) {
                int row = srow + p * 32;
                ra[p] = *(const float4*)(A + (size_t)(m0 + row) * K + k0 + sc4);
                rb[p] = *(const float4*)(B + (size_t)(n0 + row) * K + k0 + sc4);
            }
        }

        // compute on SMEM chunk
#pragma unroll
        for (int ks = 0; ks < 4; ks++) {
            uint32_t af[4][4], bf[4][2];
#pragma unroll
            for (int mt = 0; mt < 4; mt++) {
                int m = wm * 64 + mt * 16 + fr;
                af[mt][0] = As[m][ks * 8 + fc];
                af[mt][1] = As[m + 8][ks * 8 + fc];
                af[mt][2] = As[m][ks * 8 + fc + 4];
                af[mt][3] = As[m + 8][ks * 8 + fc + 4];
            }
#pragma unroll
            for (int nt = 0; nt < 4; nt++) {
                int n = wn * 32 + nt * 8 + fr;
                bf[nt][0] = Bs[n][ks * 8 + fc];
                bf[nt][1] = Bs[n][ks * 8 + fc + 4];
            }
#pragma unroll
            for (int mt = 0; mt < 4; mt++)
#pragma unroll
                for (int nt = 0; nt < 4; nt++)
                    mma_tf32(acc[mt][nt], af[mt], bf[nt]);
        }
        __syncthreads();

        if (ch + 1 < NC) {
#pragma unroll
            for (int p = 0; p < 4; p++) {
                int row = srow + p * 32;
                uint4 ta = { f2tf(ra[p].x), f2tf(ra[p].y), f2tf(ra[p].z), f2tf(ra[p].w) };
                *(uint4*)&As[row][sc4] = ta;
                uint4 tb = { f2tf(rb[p].x), f2tf(rb[p].y), f2tf(rb[p].z), f2tf(rb[p].w) };
                *(uint4*)&Bs[row][sc4] = tb;
            }
            __syncthreads();
        }
    }

    // epilogue: write accumulators (+bias)
    const int c2 = (lane & 3) * 2;
#pragma unroll
    for (int mt = 0; mt < 4; mt++) {
        int m = m0 + wm * 64 + mt * 16 + fr;
#pragma unroll
        for (int nt = 0; nt < 4; nt++) {
            int n = n0 + wn * 32 + nt * 8 + c2;
            float b0 = 0.f, b1 = 0.f;
            if (bias) { b0 = bias[n]; b1 = bias[n + 1]; }
            float2 v0 = { acc[mt][nt][0] + b0, acc[mt][nt][1] + b1 };
            float2 v1 = { acc[mt][nt][2] + b0, acc[mt][nt][3] + b1 };
            *(float2*)(C + (size_t)m * N + n)       = v0;
            *(float2*)(C + (size_t)(m + 8) * N + n) = v1;
        }
    }
}

// =====================================================================
// Flash attention with symmetric ALiBi, GQA (kv head = h/2).  (unchanged)
// =====================================================================
#define LDST 68

__global__ __launch_bounds__(256, 2)
void flash_attn()
{
    extern __shared__ float sm[];
    float* Qt = sm;
    float* Kt = Qt + 64 * LDST;
    float* Vs = Kt + 64 * LDST;
    float* Ps = Vs + 64 * LDST;

    const int tid = threadIdx.x;
    const int tx = tid & 15;
    const int ty = tid >> 4;
    const int qb = blockIdx.x;
    const int h  = blockIdx.y;
    const int n  = blockIdx.z;
    const int q0 = qb * 64;
    const int kvh = h >> 1;
    const float slope = exp2f(-(float)(h + 1));

#pragma unroll
    for (int p = 0; p < 4; p++) {
        int f4 = tid + p * 256;
        int qi = f4 >> 4;
        int d4 = f4 & 15;
        float4 a = *(const float4*)(g_q + (size_t)(n * SEQ + q0 + qi) * (NH * HD)
                                        + h * HD + d4 * 4);
        int sc = qi ^ (d4 * 4);
        Qt[(d4 * 4 + 0) * LDST + sc] = a.x;
        Qt[(d4 * 4 + 1) * LDST + sc] = a.y;
        Qt[(d4 * 4 + 2) * LDST + sc] = a.z;
        Qt[(d4 * 4 + 3) * LDST + sc] = a.w;
    }

    float m_run[4], l_run[4], acc[4][4];
#pragma unroll
    for (int i = 0; i < 4; i++) {
        m_run[i] = -INFINITY; l_run[i] = 0.f;
#pragma unroll
        for (int j = 0; j < 4; j++) acc[i][j] = 0.f;
    }

    const float tq0 = (float)(q0 + ty * 4);

    for (int kb = 0; kb < SEQ / 64; kb++) {
        __syncthreads();

#pragma unroll
        for (int p = 0; p < 4; p++) {
            int f4 = tid + p * 256;
            int ki = f4 >> 4;
            int d4 = f4 & 15;
            size_t gk = (size_t)(n * SEQ + kb * 64 + ki) * (NKV * HD) + kvh * HD + d4 * 4;
            float4 a = *(const float4*)(g_k + gk);
            int sc = ki ^ (d4 * 4);
            Kt[(d4 * 4 + 0) * LDST + sc] = a.x;
            Kt[(d4 * 4 + 1) * LDST + sc] = a.y;
            Kt[(d4 * 4 + 2) * LDST + sc] = a.z;
            Kt[(d4 * 4 + 3) * LDST + sc] = a.w;
            float4 b = *(const float4*)(g_v + gk);
            *(float4*)&Vs[ki * LDST + d4 * 4] = b;
        }
        __syncthreads();

        float s[4][4];
#pragma unroll
        for (int i = 0; i < 4; i++)
#pragma unroll
            for (int j = 0; j < 4; j++) s[i][j] = 0.f;

#pragma unroll 8
        for (int dd = 0; dd < 64; dd++) {
            int X = dd & ~3;
            float4 qv = *(const float4*)&Qt[dd * LDST + ((ty * 4) ^ X)];
            float4 kv = *(const float4*)&Kt[dd * LDST + ((tx * 4) ^ X)];
            float qa[4] = {qv.x, qv.y, qv.z, qv.w};
            float ka[4] = {kv.x, kv.y, kv.z, kv.w};
#pragma unroll
            for (int i = 0; i < 4; i++)
#pragma unroll
                for (int j = 0; j < 4; j++)
                    s[i][j] = fmaf(qa[i], ka[j], s[i][j]);
        }

        const float tk0 = (float)(kb * 64 + tx * 4);
#pragma unroll
        for (int i = 0; i < 4; i++)
#pragma unroll
            for (int j = 0; j < 4; j++) {
                float dist = fabsf((tq0 + i) - (tk0 + j));
                s[i][j] = (s[i][j] - dist * slope) * 0.125f;
            }

#pragma unroll
        for (int i = 0; i < 4; i++) {
            float mt = fmaxf(fmaxf(s[i][0], s[i][1]), fmaxf(s[i][2], s[i][3]));
#pragma unroll
            for (int msk = 1; msk < 16; msk <<= 1)
                mt = fmaxf(mt, __shfl_xor_sync(0xffffffffu, mt, msk));
            float mnew = fmaxf(m_run[i], mt);
            float corr = __expf(m_run[i] - mnew);
            m_run[i] = mnew;
            float rs = 0.f;
#pragma unroll
            for (int j = 0; j < 4; j++) {
                float pv = __expf(s[i][j] - mnew);
                s[i][j] = pv;
                rs += pv;
            }
#pragma unroll
            for (int msk = 1; msk < 16; msk <<= 1)
                rs += __shfl_xor_sync(0xffffffffu, rs, msk);
            l_run[i] = l_run[i] * corr + rs;
#pragma unroll
            for (int j = 0; j < 4; j++) acc[i][j] *= corr;
            float4 pr; pr.x = s[i][0]; pr.y = s[i][1]; pr.z = s[i][2]; pr.w = s[i][3];
            *(float4*)&Ps[(ty * 4 + i) * LDST + tx * 4] = pr;
        }
        __syncthreads();

#pragma unroll 4
        for (int k4 = 0; k4 < 16; k4++) {
            float pv[4][4];
#pragma unroll
            for (int i = 0; i < 4; i++)
                *(float4*)pv[i] = *(const float4*)&Ps[(ty * 4 + i) * LDST + k4 * 4];
#pragma unroll
            for (int c = 0; c < 4; c++) {
                float4 vv = *(const float4*)&Vs[(k4 * 4 + c) * LDST + tx * 4];
                float va[4] = {vv.x, vv.y, vv.z, vv.w};
#pragma unroll
                for (int i = 0; i < 4; i++)
#pragma unroll
                    for (int j = 0; j < 4; j++)
                        acc[i][j] = fmaf(pv[i][c], va[j], acc[i][j]);
            }
        }
    }

#pragma unroll
    for (int i = 0; i < 4; i++) {
        float inv = 1.f / l_run[i];
        float4 o;
        o.x = acc[i][0] * inv; o.y = acc[i][1] * inv;
        o.z = acc[i][2] * inv; o.w = acc[i][3] * inv;
        *(float4*)(g_attn + (size_t)(n * SEQ + q0 + ty * 4 + i) * (NH * HD)
                          + h * HD + tx * 4) = o;
    }
}

// =====================================================================
// launch
// =====================================================================
extern "C" void kernel_launch(void* const* d_in, const int* in_sizes, int n_in,
                              void* d_out, int out_size)
{
    const float* x  = (const float*)d_in[0];
    const float* Wq = (const float*)d_in[1];
    const float* Wk = (const float*)d_in[2];
    const float* Wv = (const float*)d_in[3];
    const float* Wo = (const float*)d_in[4];
    const float* bo = (const float*)d_in[5];
    float* out = (float*)d_out;

    float *qp, *kp, *vp, *ap;
    cudaGetSymbolAddress((void**)&qp, g_q);
    cudaGetSymbolAddress((void**)&kp, g_k);
    cudaGetSymbolAddress((void**)&vp, g_v);
    cudaGetSymbolAddress((void**)&ap, g_attn);

    // QKV projections (mma.sync tf32)
    gemm_mma<<<dim3((NH * HD) / 128, MROWS / 128), 256>>>(x, Wq, nullptr, qp,
                                                          MROWS, NH * HD, EMB);
    gemm_mma<<<dim3((NKV * HD) / 128, MROWS / 128), 256>>>(x, Wk, nullptr, kp,
                                                           MROWS, NKV * HD, EMB);
    gemm_mma<<<dim3((NKV * HD) / 128, MROWS / 128), 256>>>(x, Wv, nullptr, vp,
                                                           MROWS, NKV * HD, EMB);

    // attention (fp32 SIMT flash, unchanged)
    int smem = 4 * 64 * LDST * (int)sizeof(float);
    cudaFuncSetAttribute(flash_attn, cudaFuncAttributeMaxDynamicSharedMemorySize, smem);
    flash_attn<<<dim3(SEQ / 64, NH, NB), 256, smem>>>();

    // output projection + bias (mma.sync tf32)
    gemm_mma<<<dim3(EMB / 128, MROWS / 128), 256>>>(ap, Wo, bo, out,
                                                    MROWS, EMB, EMB);
}

// round 4
// speedup vs baseline: 2.4510x; 1.7717x over previous
#include <cuda_runtime.h>
#include <math.h>
#include <stdint.h>

#define NB   2
#define SEQ  2048
#define EMB  1024
#define NH   16
#define NKV  8
#define HD   64
#define MROWS (NB*SEQ)   // 4096

// ---------------- scratch (no allocations allowed) ----------------
__device__ float g_q[(size_t)MROWS * NH * HD];    // 16 MB
__device__ float g_k[(size_t)MROWS * NKV * HD];   // 8 MB
__device__ float g_v[(size_t)MROWS * NKV * HD];   // 8 MB
__device__ float g_attn[(size_t)MROWS * NH * HD]; // 16 MB

// =====================================================================
// helpers
// =====================================================================
__device__ __forceinline__ uint32_t f2tf(float f) {
    uint32_t u;
    asm("cvt.rna.tf32.f32 %0, %1;" : "=r"(u) : "f"(f));
    return u;
}
__device__ __forceinline__ void mma_tf32(float* d, const uint32_t* a, const uint32_t* b) {
    asm volatile(
        "mma.sync.aligned.m16n8k8.row.col.f32.tf32.tf32.f32 "
        "{%0,%1,%2,%3}, {%4,%5,%6,%7}, {%8,%9}, {%0,%1,%2,%3};"
        : "+f"(d[0]), "+f"(d[1]), "+f"(d[2]), "+f"(d[3])
        : "r"(a[0]), "r"(a[1]), "r"(a[2]), "r"(a[3]), "r"(b[0]), "r"(b[1]));
}

// =====================================================================
// mma.sync tf32 GEMM: C[M,N] = A[M,K] @ B[N,K]^T (+ bias[N])   (unchanged)
// =====================================================================
#define LT 36

__global__ __launch_bounds__(256)
void gemm_mma(const float* __restrict__ A, const float* __restrict__ B,
              const float* __restrict__ bias, float* __restrict__ C,
              int M, int N, int K)
{
    __shared__ uint32_t As[128][LT];
    __shared__ uint32_t Bs[128][LT];

    const int tid  = threadIdx.x;
    const int lane = tid & 31;
    const int wid  = tid >> 5;
    const int wm   = wid >> 2;
    const int wn   = wid & 3;
    const int m0   = blockIdx.y * 128;
    const int n0   = blockIdx.x * 128;

    const int srow = tid >> 3;
    const int sc4  = (tid & 7) * 4;

    float acc[4][4][4];
#pragma unroll
    for (int mt = 0; mt < 4; mt++)
#pragma unroll
        for (int nt = 0; nt < 4; nt++)
#pragma unroll
            for (int i = 0; i < 4; i++) acc[mt][nt][i] = 0.f;

    float4 ra[4], rb[4];

#pragma unroll
    for (int p = 0; p < 4; p++) {
        int row = srow + p * 32;
        ra[p] = *(const float4*)(A + (size_t)(m0 + row) * K + sc4);
        rb[p] = *(const float4*)(B + (size_t)(n0 + row) * K + sc4);
    }
#pragma unroll
    for (int p = 0; p < 4; p++) {
        int row = srow + p * 32;
        uint4 ta = { f2tf(ra[p].x), f2tf(ra[p].y), f2tf(ra[p].z), f2tf(ra[p].w) };
        *(uint4*)&As[row][sc4] = ta;
        uint4 tb = { f2tf(rb[p].x), f2tf(rb[p].y), f2tf(rb[p].z), f2tf(rb[p].w) };
        *(uint4*)&Bs[row][sc4] = tb;
    }
    __syncthreads();

    const int NC = K / 32;
    const int fr = lane >> 2;
    const int fc = lane & 3;

    for (int ch = 0; ch < NC; ch++) {
        if (ch + 1 < NC) {
            int k0 = (ch + 1) * 32;
#pragma unroll
            for (int p = 0; p < 4; p++) {
                int row = srow + p * 32;
                ra[p] = *(const float4*)(A + (size_t)(m0 + row) * K + k0 + sc4);
                rb[p] = *(const float4*)(B + (size_t)(n0 + row) * K + k0 + sc4);
            }
        }

#pragma unroll
        for (int ks = 0; ks < 4; ks++) {
            uint32_t af[4][4], bf[4][2];
#pragma unroll
            for (int mt = 0; mt < 4; mt++) {
                int m = wm * 64 + mt * 16 + fr;
                af[mt][0] = As[m][ks * 8 + fc];
                af[mt][1] = As[m + 8][ks * 8 + fc];
                af[mt][2] = As[m][ks * 8 + fc + 4];
                af[mt][3] = As[m + 8][ks * 8 + fc + 4];
            }
#pragma unroll
            for (int nt = 0; nt < 4; nt++) {
                int n = wn * 32 + nt * 8 + fr;
                bf[nt][0] = Bs[n][ks * 8 + fc];
                bf[nt][1] = Bs[n][ks * 8 + fc + 4];
            }
#pragma unroll
            for (int mt = 0; mt < 4; mt++)
#pragma unroll
                for (int nt = 0; nt < 4; nt++)
                    mma_tf32(acc[mt][nt], af[mt], bf[nt]);
        }
        __syncthreads();

        if (ch + 1 < NC) {
#pragma unroll
            for (int p = 0; p < 4; p++) {
                int row = srow + p * 32;
                uint4 ta = { f2tf(ra[p].x), f2tf(ra[p].y), f2tf(ra[p].z), f2tf(ra[p].w) };
                *(uint4*)&As[row][sc4] = ta;
                uint4 tb = { f2tf(rb[p].x), f2tf(rb[p].y), f2tf(rb[p].z), f2tf(rb[p].w) };
                *(uint4*)&Bs[row][sc4] = tb;
            }
            __syncthreads();
        }
    }

    const int c2 = (lane & 3) * 2;
#pragma unroll
    for (int mt = 0; mt < 4; mt++) {
        int m = m0 + wm * 64 + mt * 16 + fr;
#pragma unroll
        for (int nt = 0; nt < 4; nt++) {
            int n = n0 + wn * 32 + nt * 8 + c2;
            float b0 = 0.f, b1 = 0.f;
            if (bias) { b0 = bias[n]; b1 = bias[n + 1]; }
            float2 v0 = { acc[mt][nt][0] + b0, acc[mt][nt][1] + b1 };
            float2 v1 = { acc[mt][nt][2] + b0, acc[mt][nt][3] + b1 };
            *(float2*)(C + (size_t)m * N + n)       = v0;
            *(float2*)(C + (size_t)(m + 8) * N + n) = v1;
        }
    }
}

// =====================================================================
// Flash attention on tensor cores (mma.sync tf32).
// BQ=128 (8 warps x 16 rows), BK=64, D=64.
// Kt: [d][key] with XOR swizzle (col = key ^ ((d>>2)*4)), stride 68.
// Vs: [key][d] stride 68.  Ps: [q][*] stride 68 (Q staging, then P).
// =====================================================================
#define LTT 68

__global__ __launch_bounds__(256, 2)
void flash_mma()
{
    extern __shared__ uint32_t smf[];
    uint32_t* Kt = smf;                  // [64][68]
    uint32_t* Vs = Kt + 64 * LTT;        // [64][68]
    uint32_t* Ps = Vs + 64 * LTT;        // [128][68]

    const int tid  = threadIdx.x;
    const int lane = tid & 31;
    const int wid  = tid >> 5;           // 0..7 : q-rows [wid*16, wid*16+16)
    const int fr   = lane >> 2;          // 0..7
    const int fc   = lane & 3;           // 0..3

    const int q0 = blockIdx.x * 128;
    const int h  = blockIdx.y;
    const int n  = blockIdx.z;
    const int kvh = h >> 1;
    const float slope = exp2f(-(float)(h + 1));

    // ---- stage Q [q][d] into Ps (tf32), then load fragments ----
#pragma unroll
    for (int p = 0; p < 8; p++) {
        int f4 = tid + p * 256;          // 0..2047
        int qi = f4 >> 4;                // 0..127
        int d4 = f4 & 15;
        float4 a = *(const float4*)(g_q + (size_t)(n * SEQ + q0 + qi) * (NH * HD)
                                        + h * HD + d4 * 4);
        uint4 t = { f2tf(a.x), f2tf(a.y), f2tf(a.z), f2tf(a.w) };
        *(uint4*)&Ps[qi * LTT + d4 * 4] = t;
    }
    __syncthreads();

    uint32_t qf[8][4];
    {
        const int r0 = wid * 16 + fr;
#pragma unroll
        for (int ks = 0; ks < 8; ks++) {
            qf[ks][0] = Ps[r0 * LTT + ks * 8 + fc];
            qf[ks][1] = Ps[(r0 + 8) * LTT + ks * 8 + fc];
            qf[ks][2] = Ps[r0 * LTT + ks * 8 + fc + 4];
            qf[ks][3] = Ps[(r0 + 8) * LTT + ks * 8 + fc + 4];
        }
    }

    float o[8][4];
#pragma unroll
    for (int nt = 0; nt < 8; nt++)
#pragma unroll
        for (int i = 0; i < 4; i++) o[nt][i] = 0.f;
    float m0r = -INFINITY, m1r = -INFINITY, l0 = 0.f, l1 = 0.f;

    const float gq0 = (float)(q0 + wid * 16 + fr);
    const float gq1 = gq0 + 8.f;

    for (int kb = 0; kb < SEQ / 64; kb++) {
        __syncthreads();   // all warps done with Kt/Vs (and Ps of prev iter)

        // ---- stage K (transposed, swizzled) and V (tf32) ----
#pragma unroll
        for (int p = 0; p < 4; p++) {
            int f4 = tid + p * 256;
            int ki = f4 >> 4;            // 0..63
            int d4 = f4 & 15;
            size_t gk = (size_t)(n * SEQ + kb * 64 + ki) * (NKV * HD) + kvh * HD + d4 * 4;
            float4 a = *(const float4*)(g_k + gk);
            int sc = ki ^ (d4 * 4);
            Kt[(d4 * 4 + 0) * LTT + sc] = f2tf(a.x);
            Kt[(d4 * 4 + 1) * LTT + sc] = f2tf(a.y);
            Kt[(d4 * 4 + 2) * LTT + sc] = f2tf(a.z);
            Kt[(d4 * 4 + 3) * LTT + sc] = f2tf(a.w);
            float4 b = *(const float4*)(g_v + gk);
            uint4 t = { f2tf(b.x), f2tf(b.y), f2tf(b.z), f2tf(b.w) };
            *(uint4*)&Vs[ki * LTT + d4 * 4] = t;
        }
        __syncthreads();

        // ---- S = Q @ K^T  (8 n-tiles of 8 keys) ----
        float s[8][4];
#pragma unroll
        for (int nt = 0; nt < 8; nt++)
#pragma unroll
            for (int i = 0; i < 4; i++) s[nt][i] = 0.f;

#pragma unroll
        for (int ks = 0; ks < 8; ks++) {
#pragma unroll
            for (int nt = 0; nt < 8; nt++) {
                int cswz = 8 * (nt ^ ks);
                uint32_t bf[2];
                bf[0] = Kt[(ks * 8 + fc) * LTT + cswz + fr];
                bf[1] = Kt[(ks * 8 + 4 + fc) * LTT + cswz + (fr ^ 4)];
                mma_tf32(s[nt], qf[ks], bf);
            }
        }

        // ---- ALiBi + scale ----
#pragma unroll
        for (int nt = 0; nt < 8; nt++) {
            float k0f = (float)(kb * 64 + nt * 8 + 2 * fc);
            s[nt][0] = (s[nt][0] - fabsf(gq0 - k0f) * slope) * 0.125f;
            s[nt][1] = (s[nt][1] - fabsf(gq0 - (k0f + 1.f)) * slope) * 0.125f;
            s[nt][2] = (s[nt][2] - fabsf(gq1 - k0f) * slope) * 0.125f;
            s[nt][3] = (s[nt][3] - fabsf(gq1 - (k0f + 1.f)) * slope) * 0.125f;
        }

        // ---- online softmax (rows fr and fr+8 of this warp) ----
        float mt0 = -INFINITY, mt1 = -INFINITY;
#pragma unroll
        for (int nt = 0; nt < 8; nt++) {
            mt0 = fmaxf(mt0, fmaxf(s[nt][0], s[nt][1]));
            mt1 = fmaxf(mt1, fmaxf(s[nt][2], s[nt][3]));
        }
        mt0 = fmaxf(mt0, __shfl_xor_sync(0xffffffffu, mt0, 1));
        mt0 = fmaxf(mt0, __shfl_xor_sync(0xffffffffu, mt0, 2));
        mt1 = fmaxf(mt1, __shfl_xor_sync(0xffffffffu, mt1, 1));
        mt1 = fmaxf(mt1, __shfl_xor_sync(0xffffffffu, mt1, 2));

        float mn0 = fmaxf(m0r, mt0), mn1 = fmaxf(m1r, mt1);
        float c0 = __expf(m0r - mn0), c1 = __expf(m1r - mn1);
        m0r = mn0; m1r = mn1;

        float rs0 = 0.f, rs1 = 0.f;
        const int r0 = wid * 16 + fr;
#pragma unroll
        for (int nt = 0; nt < 8; nt++) {
            float p0 = __expf(s[nt][0] - mn0);
            float p1 = __expf(s[nt][1] - mn0);
            float p2 = __expf(s[nt][2] - mn1);
            float p3 = __expf(s[nt][3] - mn1);
            rs0 += p0 + p1; rs1 += p2 + p3;
            uint2 w0 = { f2tf(p0), f2tf(p1) };
            uint2 w1 = { f2tf(p2), f2tf(p3) };
            *(uint2*)&Ps[r0 * LTT + nt * 8 + 2 * fc]       = w0;
            *(uint2*)&Ps[(r0 + 8) * LTT + nt * 8 + 2 * fc] = w1;
        }
        rs0 += __shfl_xor_sync(0xffffffffu, rs0, 1);
        rs0 += __shfl_xor_sync(0xffffffffu, rs0, 2);
        rs1 += __shfl_xor_sync(0xffffffffu, rs1, 1);
        rs1 += __shfl_xor_sync(0xffffffffu, rs1, 2);
        l0 = l0 * c0 + rs0;
        l1 = l1 * c1 + rs1;

#pragma unroll
        for (int nt = 0; nt < 8; nt++) {
            o[nt][0] *= c0; o[nt][1] *= c0;
            o[nt][2] *= c1; o[nt][3] *= c1;
        }
        __syncwarp();   // P visible to own warp's lanes

        // ---- O += P @ V ----
#pragma unroll
        for (int ks = 0; ks < 8; ks++) {
            uint32_t af[4];
            af[0] = Ps[r0 * LTT + ks * 8 + fc];
            af[1] = Ps[(r0 + 8) * LTT + ks * 8 + fc];
            af[2] = Ps[r0 * LTT + ks * 8 + fc + 4];
            af[3] = Ps[(r0 + 8) * LTT + ks * 8 + fc + 4];
#pragma unroll
            for (int nt = 0; nt < 8; nt++) {
                uint32_t bf[2];
                bf[0] = Vs[(ks * 8 + fc) * LTT + nt * 8 + fr];
                bf[1] = Vs[(ks * 8 + fc + 4) * LTT + nt * 8 + fr];
                mma_tf32(o[nt], af, bf);
            }
        }
    }

    // ---- normalize + write ----
    {
        float inv0 = 1.f / l0, inv1 = 1.f / l1;
        const int qr0 = q0 + wid * 16 + fr;
        float* base0 = g_attn + (size_t)(n * SEQ + qr0) * (NH * HD) + h * HD;
        float* base1 = g_attn + (size_t)(n * SEQ + qr0 + 8) * (NH * HD) + h * HD;
#pragma unroll
        for (int nt = 0; nt < 8; nt++) {
            float2 w0 = { o[nt][0] * inv0, o[nt][1] * inv0 };
            float2 w1 = { o[nt][2] * inv1, o[nt][3] * inv1 };
            *(float2*)(base0 + nt * 8 + 2 * fc) = w0;
            *(float2*)(base1 + nt * 8 + 2 * fc) = w1;
        }
    }
}

// =====================================================================
// launch
// =====================================================================
extern "C" void kernel_launch(void* const* d_in, const int* in_sizes, int n_in,
                              void* d_out, int out_size)
{
    const float* x  = (const float*)d_in[0];
    const float* Wq = (const float*)d_in[1];
    const float* Wk = (const float*)d_in[2];
    const float* Wv = (const float*)d_in[3];
    const float* Wo = (const float*)d_in[4];
    const float* bo = (const float*)d_in[5];
    float* out = (float*)d_out;

    float *qp, *kp, *vp, *ap;
    cudaGetSymbolAddress((void**)&qp, g_q);
    cudaGetSymbolAddress((void**)&kp, g_k);
    cudaGetSymbolAddress((void**)&vp, g_v);
    cudaGetSymbolAddress((void**)&ap, g_attn);

    // QKV projections (mma.sync tf32)
    gemm_mma<<<dim3((NH * HD) / 128, MROWS / 128), 256>>>(x, Wq, nullptr, qp,
                                                          MROWS, NH * HD, EMB);
    gemm_mma<<<dim3((NKV * HD) / 128, MROWS / 128), 256>>>(x, Wk, nullptr, kp,
                                                           MROWS, NKV * HD, EMB);
    gemm_mma<<<dim3((NKV * HD) / 128, MROWS / 128), 256>>>(x, Wv, nullptr, vp,
                                                           MROWS, NKV * HD, EMB);

    // attention (mma.sync tf32 flash)
    int smemf = (64 + 64 + 128) * LTT * (int)sizeof(uint32_t);   // 69632
    cudaFuncSetAttribute(flash_mma, cudaFuncAttributeMaxDynamicSharedMemorySize, smemf);
    flash_mma<<<dim3(SEQ / 128, NH, NB), 256, smemf>>>();

    // output projection + bias (mma.sync tf32)
    gemm_mma<<<dim3(EMB / 128, MROWS / 128), 256>>>(ap, Wo, bo, out,
                                                    MROWS, EMB, EMB);
}

// round 5
// speedup vs baseline: 3.0239x; 1.2337x over previous
#include <cuda_runtime.h>
#include <math.h>
#include <stdint.h>

#define NB   2
#define SEQ  2048
#define EMB  1024
#define NH   16
#define NKV  8
#define HD   64
#define MROWS (NB*SEQ)   // 4096

// ---------------- scratch (no allocations allowed) ----------------
__device__ float g_q[(size_t)MROWS * NH * HD];    // 16 MB
__device__ float g_k[(size_t)MROWS * NKV * HD];   // 8 MB
__device__ float g_v[(size_t)MROWS * NKV * HD];   // 8 MB
__device__ float g_attn[(size_t)MROWS * NH * HD]; // 16 MB

// =====================================================================
// helpers
// =====================================================================
__device__ __forceinline__ uint32_t f2tf(float f) {
    uint32_t u;
    asm("cvt.rna.tf32.f32 %0, %1;" : "=r"(u) : "f"(f));
    return u;
}
__device__ __forceinline__ void mma_tf32(float* d, const uint32_t* a, const uint32_t* b) {
    asm volatile(
        "mma.sync.aligned.m16n8k8.row.col.f32.tf32.tf32.f32 "
        "{%0,%1,%2,%3}, {%4,%5,%6,%7}, {%8,%9}, {%0,%1,%2,%3};"
        : "+f"(d[0]), "+f"(d[1]), "+f"(d[2]), "+f"(d[3])
        : "r"(a[0]), "r"(a[1]), "r"(a[2]), "r"(a[3]), "r"(b[0]), "r"(b[1]));
}

// =====================================================================
// mma.sync tf32 GEMM: C[M,N] = A[M,K] @ B[N,K]^T (+ bias[N])   (unchanged)
// =====================================================================
#define LT 36

__global__ __launch_bounds__(256)
void gemm_mma(const float* __restrict__ A, const float* __restrict__ B,
              const float* __restrict__ bias, float* __restrict__ C,
              int M, int N, int K)
{
    __shared__ uint32_t As[128][LT];
    __shared__ uint32_t Bs[128][LT];

    const int tid  = threadIdx.x;
    const int lane = tid & 31;
    const int wid  = tid >> 5;
    const int wm   = wid >> 2;
    const int wn   = wid & 3;
    const int m0   = blockIdx.y * 128;
    const int n0   = blockIdx.x * 128;

    const int srow = tid >> 3;
    const int sc4  = (tid & 7) * 4;

    float acc[4][4][4];
#pragma unroll
    for (int mt = 0; mt < 4; mt++)
#pragma unroll
        for (int nt = 0; nt < 4; nt++)
#pragma unroll
            for (int i = 0; i < 4; i++) acc[mt][nt][i] = 0.f;

    float4 ra[4], rb[4];

#pragma unroll
    for (int p = 0; p < 4; p++) {
        int row = srow + p * 32;
        ra[p] = *(const float4*)(A + (size_t)(m0 + row) * K + sc4);
        rb[p] = *(const float4*)(B + (size_t)(n0 + row) * K + sc4);
    }
#pragma unroll
    for (int p = 0; p < 4; p++) {
        int row = srow + p * 32;
        uint4 ta = { f2tf(ra[p].x), f2tf(ra[p].y), f2tf(ra[p].z), f2tf(ra[p].w) };
        *(uint4*)&As[row][sc4] = ta;
        uint4 tb = { f2tf(rb[p].x), f2tf(rb[p].y), f2tf(rb[p].z), f2tf(rb[p].w) };
        *(uint4*)&Bs[row][sc4] = tb;
    }
    __syncthreads();

    const int NC = K / 32;
    const int fr = lane >> 2;
    const int fc = lane & 3;

    for (int ch = 0; ch < NC; ch++) {
        if (ch + 1 < NC) {
            int k0 = (ch + 1) * 32;
#pragma unroll
            for (int p = 0; p < 4; p++) {
                int row = srow + p * 32;
                ra[p] = *(const float4*)(A + (size_t)(m0 + row) * K + k0 + sc4);
                rb[p] = *(const float4*)(B + (size_t)(n0 + row) * K + k0 + sc4);
            }
        }

#pragma unroll
        for (int ks = 0; ks < 4; ks++) {
            uint32_t af[4][4], bf[4][2];
#pragma unroll
            for (int mt = 0; mt < 4; mt++) {
                int m = wm * 64 + mt * 16 + fr;
                af[mt][0] = As[m][ks * 8 + fc];
                af[mt][1] = As[m + 8][ks * 8 + fc];
                af[mt][2] = As[m][ks * 8 + fc + 4];
                af[mt][3] = As[m + 8][ks * 8 + fc + 4];
            }
#pragma unroll
            for (int nt = 0; nt < 4; nt++) {
                int n = wn * 32 + nt * 8 + fr;
                bf[nt][0] = Bs[n][ks * 8 + fc];
                bf[nt][1] = Bs[n][ks * 8 + fc + 4];
            }
#pragma unroll
            for (int mt = 0; mt < 4; mt++)
#pragma unroll
                for (int nt = 0; nt < 4; nt++)
                    mma_tf32(acc[mt][nt], af[mt], bf[nt]);
        }
        __syncthreads();

        if (ch + 1 < NC) {
#pragma unroll
            for (int p = 0; p < 4; p++) {
                int row = srow + p * 32;
                uint4 ta = { f2tf(ra[p].x), f2tf(ra[p].y), f2tf(ra[p].z), f2tf(ra[p].w) };
                *(uint4*)&As[row][sc4] = ta;
                uint4 tb = { f2tf(rb[p].x), f2tf(rb[p].y), f2tf(rb[p].z), f2tf(rb[p].w) };
                *(uint4*)&Bs[row][sc4] = tb;
            }
            __syncthreads();
        }
    }

    const int c2 = (lane & 3) * 2;
#pragma unroll
    for (int mt = 0; mt < 4; mt++) {
        int m = m0 + wm * 64 + mt * 16 + fr;
#pragma unroll
        for (int nt = 0; nt < 4; nt++) {
            int n = n0 + wn * 32 + nt * 8 + c2;
            float b0 = 0.f, b1 = 0.f;
            if (bias) { b0 = bias[n]; b1 = bias[n + 1]; }
            float2 v0 = { acc[mt][nt][0] + b0, acc[mt][nt][1] + b1 };
            float2 v1 = { acc[mt][nt][2] + b0, acc[mt][nt][3] + b1 };
            *(float2*)(C + (size_t)m * N + n)       = v0;
            *(float2*)(C + (size_t)(m + 8) * N + n) = v1;
        }
    }
}

// =====================================================================
// Flash attention on tensor cores (mma.sync tf32), v2:
// 4 warps x 32 q-rows (BQ=128), BK=64. K/V fragments reused across the
// two 16-row mma blocks of each warp -> ~1.65x fewer LDS per mma.
// Kt: [d][key] XOR-swizzled, stride 68.  Vs: [key][d] stride 68.
// Ps: [q][*] stride 68 (Q staging at start, then P each iter).
// =====================================================================
#define LTT 68

__global__ __launch_bounds__(128, 2)
void flash_mma()
{
    extern __shared__ uint32_t smf[];
    uint32_t* Kt = smf;                  // [64][68]
    uint32_t* Vs = Kt + 64 * LTT;        // [64][68]
    uint32_t* Ps = Vs + 64 * LTT;        // [128][68]

    const int tid  = threadIdx.x;
    const int lane = tid & 31;
    const int wid  = tid >> 5;           // 0..3 : q-rows [wid*32, wid*32+32)
    const int fr   = lane >> 2;          // 0..7
    const int fc   = lane & 3;           // 0..3

    const int q0 = blockIdx.x * 128;
    const int h  = blockIdx.y;
    const int n  = blockIdx.z;
    const int kvh = h >> 1;
    const float slope = exp2f(-(float)(h + 1));

    // ---- stage Q [q][d] into Ps (tf32) ----
#pragma unroll
    for (int p = 0; p < 16; p++) {
        int f4 = tid + p * 128;          // 0..2047
        int qi = f4 >> 4;                // 0..127
        int d4 = f4 & 15;
        float4 a = *(const float4*)(g_q + (size_t)(n * SEQ + q0 + qi) * (NH * HD)
                                        + h * HD + d4 * 4);
        uint4 t = { f2tf(a.x), f2tf(a.y), f2tf(a.z), f2tf(a.w) };
        *(uint4*)&Ps[qi * LTT + d4 * 4] = t;
    }
    __syncthreads();

    const int r0 = wid * 32 + fr;        // block0 rows r0, r0+8; block1 rows r0+16, r0+24
    uint32_t qf0[8][4], qf1[8][4];
#pragma unroll
    for (int ks = 0; ks < 8; ks++) {
        qf0[ks][0] = Ps[r0 * LTT + ks * 8 + fc];
        qf0[ks][1] = Ps[(r0 + 8) * LTT + ks * 8 + fc];
        qf0[ks][2] = Ps[r0 * LTT + ks * 8 + fc + 4];
        qf0[ks][3] = Ps[(r0 + 8) * LTT + ks * 8 + fc + 4];
        qf1[ks][0] = Ps[(r0 + 16) * LTT + ks * 8 + fc];
        qf1[ks][1] = Ps[(r0 + 24) * LTT + ks * 8 + fc];
        qf1[ks][2] = Ps[(r0 + 16) * LTT + ks * 8 + fc + 4];
        qf1[ks][3] = Ps[(r0 + 24) * LTT + ks * 8 + fc + 4];
    }

    float o0[8][4], o1[8][4];
#pragma unroll
    for (int nt = 0; nt < 8; nt++)
#pragma unroll
        for (int i = 0; i < 4; i++) { o0[nt][i] = 0.f; o1[nt][i] = 0.f; }
    float m00 = -INFINITY, m01 = -INFINITY, m10 = -INFINITY, m11 = -INFINITY;
    float l00 = 0.f, l01 = 0.f, l10 = 0.f, l11 = 0.f;

    const float gq0 = (float)(q0 + wid * 32 + fr);   // block0 row a
    // rows: gq0, gq0+8 (block0), gq0+16, gq0+24 (block1)

    for (int kb = 0; kb < SEQ / 64; kb++) {
        __syncthreads();   // all warps done with Kt/Vs/Ps of prev iter

        // ---- stage K (transposed, swizzled) and V (tf32) ----
#pragma unroll
        for (int p = 0; p < 8; p++) {
            int f4 = tid + p * 128;
            int ki = f4 >> 4;            // 0..63
            int d4 = f4 & 15;
            size_t gk = (size_t)(n * SEQ + kb * 64 + ki) * (NKV * HD) + kvh * HD + d4 * 4;
            float4 a = *(const float4*)(g_k + gk);
            int sc = ki ^ (d4 * 4);
            Kt[(d4 * 4 + 0) * LTT + sc] = f2tf(a.x);
            Kt[(d4 * 4 + 1) * LTT + sc] = f2tf(a.y);
            Kt[(d4 * 4 + 2) * LTT + sc] = f2tf(a.z);
            Kt[(d4 * 4 + 3) * LTT + sc] = f2tf(a.w);
            float4 b = *(const float4*)(g_v + gk);
            uint4 t = { f2tf(b.x), f2tf(b.y), f2tf(b.z), f2tf(b.w) };
            *(uint4*)&Vs[ki * LTT + d4 * 4] = t;
        }
        __syncthreads();

        // ---- S = Q @ K^T for both 16-row blocks, K frags loaded once ----
        float s0[8][4], s1[8][4];
#pragma unroll
        for (int nt = 0; nt < 8; nt++)
#pragma unroll
            for (int i = 0; i < 4; i++) { s0[nt][i] = 0.f; s1[nt][i] = 0.f; }

#pragma unroll
        for (int ks = 0; ks < 8; ks++) {
            uint32_t bf[8][2];
#pragma unroll
            for (int nt = 0; nt < 8; nt++) {
                int cswz = 8 * (nt ^ ks);
                bf[nt][0] = Kt[(ks * 8 + fc) * LTT + cswz + fr];
                bf[nt][1] = Kt[(ks * 8 + 4 + fc) * LTT + cswz + (fr ^ 4)];
            }
#pragma unroll
            for (int nt = 0; nt < 8; nt++) {
                mma_tf32(s0[nt], qf0[ks], bf[nt]);
                mma_tf32(s1[nt], qf1[ks], bf[nt]);
            }
        }

        // ---- ALiBi + scale ----
#pragma unroll
        for (int nt = 0; nt < 8; nt++) {
            float k0f = (float)(kb * 64 + nt * 8 + 2 * fc);
            float k1f = k0f + 1.f;
            s0[nt][0] = (s0[nt][0] - fabsf(gq0 - k0f) * slope) * 0.125f;
            s0[nt][1] = (s0[nt][1] - fabsf(gq0 - k1f) * slope) * 0.125f;
            s0[nt][2] = (s0[nt][2] - fabsf((gq0 + 8.f) - k0f) * slope) * 0.125f;
            s0[nt][3] = (s0[nt][3] - fabsf((gq0 + 8.f) - k1f) * slope) * 0.125f;
            s1[nt][0] = (s1[nt][0] - fabsf((gq0 + 16.f) - k0f) * slope) * 0.125f;
            s1[nt][1] = (s1[nt][1] - fabsf((gq0 + 16.f) - k1f) * slope) * 0.125f;
            s1[nt][2] = (s1[nt][2] - fabsf((gq0 + 24.f) - k0f) * slope) * 0.125f;
            s1[nt][3] = (s1[nt][3] - fabsf((gq0 + 24.f) - k1f) * slope) * 0.125f;
        }

        // ---- online softmax, block0 (rows fr, fr+8) ----
        {
            float mt0 = -INFINITY, mt1 = -INFINITY;
#pragma unroll
            for (int nt = 0; nt < 8; nt++) {
                mt0 = fmaxf(mt0, fmaxf(s0[nt][0], s0[nt][1]));
                mt1 = fmaxf(mt1, fmaxf(s0[nt][2], s0[nt][3]));
            }
            mt0 = fmaxf(mt0, __shfl_xor_sync(0xffffffffu, mt0, 1));
            mt0 = fmaxf(mt0, __shfl_xor_sync(0xffffffffu, mt0, 2));
            mt1 = fmaxf(mt1, __shfl_xor_sync(0xffffffffu, mt1, 1));
            mt1 = fmaxf(mt1, __shfl_xor_sync(0xffffffffu, mt1, 2));
            float mn0 = fmaxf(m00, mt0), mn1 = fmaxf(m01, mt1);
            float c0 = __expf(m00 - mn0), c1 = __expf(m01 - mn1);
            m00 = mn0; m01 = mn1;
            float rs0 = 0.f, rs1 = 0.f;
#pragma unroll
            for (int nt = 0; nt < 8; nt++) {
                float p0 = __expf(s0[nt][0] - mn0);
                float p1 = __expf(s0[nt][1] - mn0);
                float p2 = __expf(s0[nt][2] - mn1);
                float p3 = __expf(s0[nt][3] - mn1);
                rs0 += p0 + p1; rs1 += p2 + p3;
                uint2 w0 = { f2tf(p0), f2tf(p1) };
                uint2 w1 = { f2tf(p2), f2tf(p3) };
                *(uint2*)&Ps[r0 * LTT + nt * 8 + 2 * fc]       = w0;
                *(uint2*)&Ps[(r0 + 8) * LTT + nt * 8 + 2 * fc] = w1;
            }
            rs0 += __shfl_xor_sync(0xffffffffu, rs0, 1);
            rs0 += __shfl_xor_sync(0xffffffffu, rs0, 2);
            rs1 += __shfl_xor_sync(0xffffffffu, rs1, 1);
            rs1 += __shfl_xor_sync(0xffffffffu, rs1, 2);
            l00 = l00 * c0 + rs0;
            l01 = l01 * c1 + rs1;
#pragma unroll
            for (int nt = 0; nt < 8; nt++) {
                o0[nt][0] *= c0; o0[nt][1] *= c0;
                o0[nt][2] *= c1; o0[nt][3] *= c1;
            }
        }
        // ---- online softmax, block1 (rows fr+16, fr+24) ----
        {
            float mt0 = -INFINITY, mt1 = -INFINITY;
#pragma unroll
            for (int nt = 0; nt < 8; nt++) {
                mt0 = fmaxf(mt0, fmaxf(s1[nt][0], s1[nt][1]));
                mt1 = fmaxf(mt1, fmaxf(s1[nt][2], s1[nt][3]));
            }
            mt0 = fmaxf(mt0, __shfl_xor_sync(0xffffffffu, mt0, 1));
            mt0 = fmaxf(mt0, __shfl_xor_sync(0xffffffffu, mt0, 2));
            mt1 = fmaxf(mt1, __shfl_xor_sync(0xffffffffu, mt1, 1));
            mt1 = fmaxf(mt1, __shfl_xor_sync(0xffffffffu, mt1, 2));
            float mn0 = fmaxf(m10, mt0), mn1 = fmaxf(m11, mt1);
            float c0 = __expf(m10 - mn0), c1 = __expf(m11 - mn1);
            m10 = mn0; m11 = mn1;
            float rs0 = 0.f, rs1 = 0.f;
#pragma unroll
            for (int nt = 0; nt < 8; nt++) {
                float p0 = __expf(s1[nt][0] - mn0);
                float p1 = __expf(s1[nt][1] - mn0);
                float p2 = __expf(s1[nt][2] - mn1);
                float p3 = __expf(s1[nt][3] - mn1);
                rs0 += p0 + p1; rs1 += p2 + p3;
                uint2 w0 = { f2tf(p0), f2tf(p1) };
                uint2 w1 = { f2tf(p2), f2tf(p3) };
                *(uint2*)&Ps[(r0 + 16) * LTT + nt * 8 + 2 * fc] = w0;
                *(uint2*)&Ps[(r0 + 24) * LTT + nt * 8 + 2 * fc] = w1;
            }
            rs0 += __shfl_xor_sync(0xffffffffu, rs0, 1);
            rs0 += __shfl_xor_sync(0xffffffffu, rs0, 2);
            rs1 += __shfl_xor_sync(0xffffffffu, rs1, 1);
            rs1 += __shfl_xor_sync(0xffffffffu, rs1, 2);
            l10 = l10 * c0 + rs0;
            l11 = l11 * c1 + rs1;
#pragma unroll
            for (int nt = 0; nt < 8; nt++) {
                o1[nt][0] *= c0; o1[nt][1] *= c0;
                o1[nt][2] *= c1; o1[nt][3] *= c1;
            }
        }
        __syncwarp();   // P visible to own warp's lanes

        // ---- O += P @ V, V frags loaded once per ks for both blocks ----
#pragma unroll
        for (int ks = 0; ks < 8; ks++) {
            uint32_t af0[4], af1[4], bf[8][2];
            af0[0] = Ps[r0 * LTT + ks * 8 + fc];
            af0[1] = Ps[(r0 + 8) * LTT + ks * 8 + fc];
            af0[2] = Ps[r0 * LTT + ks * 8 + fc + 4];
            af0[3] = Ps[(r0 + 8) * LTT + ks * 8 + fc + 4];
            af1[0] = Ps[(r0 + 16) * LTT + ks * 8 + fc];
            af1[1] = Ps[(r0 + 24) * LTT + ks * 8 + fc];
            af1[2] = Ps[(r0 + 16) * LTT + ks * 8 + fc + 4];
            af1[3] = Ps[(r0 + 24) * LTT + ks * 8 + fc + 4];
#pragma unroll
            for (int nt = 0; nt < 8; nt++) {
                bf[nt][0] = Vs[(ks * 8 + fc) * LTT + nt * 8 + fr];
                bf[nt][1] = Vs[(ks * 8 + fc + 4) * LTT + nt * 8 + fr];
            }
#pragma unroll
            for (int nt = 0; nt < 8; nt++) {
                mma_tf32(o0[nt], af0, bf[nt]);
                mma_tf32(o1[nt], af1, bf[nt]);
            }
        }
    }

    // ---- normalize + write (4 rows per thread-group) ----
    {
        float i00 = 1.f / l00, i01 = 1.f / l01, i10 = 1.f / l10, i11 = 1.f / l11;
        const int qr = q0 + wid * 32 + fr;
        float* b0 = g_attn + (size_t)(n * SEQ + qr) * (NH * HD) + h * HD;
        float* b1 = g_attn + (size_t)(n * SEQ + qr + 8) * (NH * HD) + h * HD;
        float* b2 = g_attn + (size_t)(n * SEQ + qr + 16) * (NH * HD) + h * HD;
        float* b3 = g_attn + (size_t)(n * SEQ + qr + 24) * (NH * HD) + h * HD;
#pragma unroll
        for (int nt = 0; nt < 8; nt++) {
            float2 w0 = { o0[nt][0] * i00, o0[nt][1] * i00 };
            float2 w1 = { o0[nt][2] * i01, o0[nt][3] * i01 };
            float2 w2 = { o1[nt][0] * i10, o1[nt][1] * i10 };
            float2 w3 = { o1[nt][2] * i11, o1[nt][3] * i11 };
            *(float2*)(b0 + nt * 8 + 2 * fc) = w0;
            *(float2*)(b1 + nt * 8 + 2 * fc) = w1;
            *(float2*)(b2 + nt * 8 + 2 * fc) = w2;
            *(float2*)(b3 + nt * 8 + 2 * fc) = w3;
        }
    }
}

// =====================================================================
// launch
// =====================================================================
extern "C" void kernel_launch(void* const* d_in, const int* in_sizes, int n_in,
                              void* d_out, int out_size)
{
    const float* x  = (const float*)d_in[0];
    const float* Wq = (const float*)d_in[1];
    const float* Wk = (const float*)d_in[2];
    const float* Wv = (const float*)d_in[3];
    const float* Wo = (const float*)d_in[4];
    const float* bo = (const float*)d_in[5];
    float* out = (float*)d_out;

    float *qp, *kp, *vp, *ap;
    cudaGetSymbolAddress((void**)&qp, g_q);
    cudaGetSymbolAddress((void**)&kp, g_k);
    cudaGetSymbolAddress((void**)&vp, g_v);
    cudaGetSymbolAddress((void**)&ap, g_attn);

    // QKV projections (mma.sync tf32)
    gemm_mma<<<dim3((NH * HD) / 128, MROWS / 128), 256>>>(x, Wq, nullptr, qp,
                                                          MROWS, NH * HD, EMB);
    gemm_mma<<<dim3((NKV * HD) / 128, MROWS / 128), 256>>>(x, Wk, nullptr, kp,
                                                           MROWS, NKV * HD, EMB);
    gemm_mma<<<dim3((NKV * HD) / 128, MROWS / 128), 256>>>(x, Wv, nullptr, vp,
                                                           MROWS, NKV * HD, EMB);

    // attention (mma.sync tf32 flash, 4 warps x 32 rows)
    int smemf = (64 + 64 + 128) * LTT * (int)sizeof(uint32_t);   // 69632
    cudaFuncSetAttribute(flash_mma, cudaFuncAttributeMaxDynamicSharedMemorySize, smemf);
    flash_mma<<<dim3(SEQ / 128, NH, NB), 128, smemf>>>();

    // output projection + bias (mma.sync tf32)
    gemm_mma<<<dim3(EMB / 128, MROWS / 128), 256>>>(ap, Wo, bo, out,
                                                    MROWS, EMB, EMB);
}

// round 6
// speedup vs baseline: 3.2390x; 1.0711x over previous
#include <cuda_runtime.h>
#include <math.h>
#include <stdint.h>

#define NB   2
#define SEQ  2048
#define EMB  1024
#define NH   16
#define NKV  8
#define HD   64
#define MROWS (NB*SEQ)   // 4096

// ---------------- scratch (no allocations allowed) ----------------
__device__ float g_q[(size_t)MROWS * NH * HD];    // 16 MB
__device__ float g_k[(size_t)MROWS * NKV * HD];   // 8 MB
__device__ float g_v[(size_t)MROWS * NKV * HD];   // 8 MB
__device__ float g_attn[(size_t)MROWS * NH * HD]; // 16 MB

// =====================================================================
// helpers
// =====================================================================
__device__ __forceinline__ uint32_t f2tf(float f) {
    uint32_t u;
    asm("cvt.rna.tf32.f32 %0, %1;" : "=r"(u) : "f"(f));
    return u;
}
__device__ __forceinline__ void mma_tf32(float* d, const uint32_t* a, const uint32_t* b) {
    asm volatile(
        "mma.sync.aligned.m16n8k8.row.col.f32.tf32.tf32.f32 "
        "{%0,%1,%2,%3}, {%4,%5,%6,%7}, {%8,%9}, {%0,%1,%2,%3};"
        : "+f"(d[0]), "+f"(d[1]), "+f"(d[2]), "+f"(d[3])
        : "r"(a[0]), "r"(a[1]), "r"(a[2]), "r"(a[3]), "r"(b[0]), "r"(b[1]));
}

// =====================================================================
// mma.sync tf32 GEMM body: C[M,N] = A[M,K] @ B[N,K]^T (+ bias[N])
// Block tile 128x128, K-chunk 32, 8 warps (2x4), warp tile 64x32.
// =====================================================================
#define LT 36

__device__ __forceinline__
void gemm_body(const float* __restrict__ A, const float* __restrict__ B,
               const float* __restrict__ bias, float* __restrict__ C,
               int N, int K, int m0, int n0)
{
    __shared__ uint32_t As[128][LT];
    __shared__ uint32_t Bs[128][LT];

    const int tid  = threadIdx.x;
    const int lane = tid & 31;
    const int wid  = tid >> 5;
    const int wm   = wid >> 2;
    const int wn   = wid & 3;

    const int srow = tid >> 3;
    const int sc4  = (tid & 7) * 4;

    float acc[4][4][4];
#pragma unroll
    for (int mt = 0; mt < 4; mt++)
#pragma unroll
        for (int nt = 0; nt < 4; nt++)
#pragma unroll
            for (int i = 0; i < 4; i++) acc[mt][nt][i] = 0.f;

    float4 ra[4], rb[4];

#pragma unroll
    for (int p = 0; p < 4; p++) {
        int row = srow + p * 32;
        ra[p] = *(const float4*)(A + (size_t)(m0 + row) * K + sc4);
        rb[p] = *(const float4*)(B + (size_t)(n0 + row) * K + sc4);
    }
#pragma unroll
    for (int p = 0; p < 4; p++) {
        int row = srow + p * 32;
        uint4 ta = { f2tf(ra[p].x), f2tf(ra[p].y), f2tf(ra[p].z), f2tf(ra[p].w) };
        *(uint4*)&As[row][sc4] = ta;
        uint4 tb = { f2tf(rb[p].x), f2tf(rb[p].y), f2tf(rb[p].z), f2tf(rb[p].w) };
        *(uint4*)&Bs[row][sc4] = tb;
    }
    __syncthreads();

    const int NC = K / 32;
    const int fr = lane >> 2;
    const int fc = lane & 3;

    for (int ch = 0; ch < NC; ch++) {
        if (ch + 1 < NC) {
            int k0 = (ch + 1) * 32;
#pragma unroll
            for (int p = 0; p < 4; p++) {
                int row = srow + p * 32;
                ra[p] = *(const float4*)(A + (size_t)(m0 + row) * K + k0 + sc4);
                rb[p] = *(const float4*)(B + (size_t)(n0 + row) * K + k0 + sc4);
            }
        }

#pragma unroll
        for (int ks = 0; ks < 4; ks++) {
            uint32_t af[4][4], bf[4][2];
#pragma unroll
            for (int mt = 0; mt < 4; mt++) {
                int m = wm * 64 + mt * 16 + fr;
                af[mt][0] = As[m][ks * 8 + fc];
                af[mt][1] = As[m + 8][ks * 8 + fc];
                af[mt][2] = As[m][ks * 8 + fc + 4];
                af[mt][3] = As[m + 8][ks * 8 + fc + 4];
            }
#pragma unroll
            for (int nt = 0; nt < 4; nt++) {
                int n = wn * 32 + nt * 8 + fr;
                bf[nt][0] = Bs[n][ks * 8 + fc];
                bf[nt][1] = Bs[n][ks * 8 + fc + 4];
            }
#pragma unroll
            for (int mt = 0; mt < 4; mt++)
#pragma unroll
                for (int nt = 0; nt < 4; nt++)
                    mma_tf32(acc[mt][nt], af[mt], bf[nt]);
        }
        __syncthreads();

        if (ch + 1 < NC) {
#pragma unroll
            for (int p = 0; p < 4; p++) {
                int row = srow + p * 32;
                uint4 ta = { f2tf(ra[p].x), f2tf(ra[p].y), f2tf(ra[p].z), f2tf(ra[p].w) };
                *(uint4*)&As[row][sc4] = ta;
                uint4 tb = { f2tf(rb[p].x), f2tf(rb[p].y), f2tf(rb[p].z), f2tf(rb[p].w) };
                *(uint4*)&Bs[row][sc4] = tb;
            }
            __syncthreads();
        }
    }

    const int c2 = (lane & 3) * 2;
#pragma unroll
    for (int mt = 0; mt < 4; mt++) {
        int m = m0 + wm * 64 + mt * 16 + fr;
#pragma unroll
        for (int nt = 0; nt < 4; nt++) {
            int n = n0 + wn * 32 + nt * 8 + c2;
            float b0 = 0.f, b1 = 0.f;
            if (bias) { b0 = bias[n]; b1 = bias[n + 1]; }
            float2 v0 = { acc[mt][nt][0] + b0, acc[mt][nt][1] + b1 };
            float2 v1 = { acc[mt][nt][2] + b0, acc[mt][nt][3] + b1 };
            *(float2*)(C + (size_t)m * N + n)       = v0;
            *(float2*)(C + (size_t)(m + 8) * N + n) = v1;
        }
    }
}

// fused QKV: blockIdx.x 0..7 -> Q, 8..11 -> K, 12..15 -> V
__global__ __launch_bounds__(256)
void gemm_qkv(const float* __restrict__ x,
              const float* __restrict__ Wq, const float* __restrict__ Wk,
              const float* __restrict__ Wv,
              float* __restrict__ q, float* __restrict__ k, float* __restrict__ v)
{
    const int bx = blockIdx.x;
    const int m0 = blockIdx.y * 128;
    if (bx < 8)       gemm_body(x, Wq, nullptr, q, NH * HD,  EMB, m0, bx * 128);
    else if (bx < 12) gemm_body(x, Wk, nullptr, k, NKV * HD, EMB, m0, (bx - 8) * 128);
    else              gemm_body(x, Wv, nullptr, v, NKV * HD, EMB, m0, (bx - 12) * 128);
}

__global__ __launch_bounds__(256)
void gemm_mma(const float* __restrict__ A, const float* __restrict__ B,
              const float* __restrict__ bias, float* __restrict__ C,
              int M, int N, int K)
{
    gemm_body(A, B, bias, C, N, K, blockIdx.y * 128, blockIdx.x * 128);
}

// =====================================================================
// Flash attention on tensor cores (mma.sync tf32), v3:
// 4 warps x 32 q-rows (BQ=128), BK=64.
// Kt/Vs row stride 72 -> fragment-load bank = 8*fc + fr (conflict-free).
// Ps stride 68 (bank = 4*fr + fc, conflict-free for qf/af/P patterns).
// =====================================================================
#define LTK 72
#define LTT 68

__global__ __launch_bounds__(128, 2)
void flash_mma()
{
    extern __shared__ uint32_t smf[];
    uint32_t* Kt = smf;                  // [64][72] d-major, XOR-swizzled cols
    uint32_t* Vs = Kt + 64 * LTK;        // [64][72] k-major
    uint32_t* Ps = Vs + 64 * LTK;        // [128][68] q-major (Q staging, then P)

    const int tid  = threadIdx.x;
    const int lane = tid & 31;
    const int wid  = tid >> 5;           // 0..3 : q-rows [wid*32, wid*32+32)
    const int fr   = lane >> 2;          // 0..7
    const int fc   = lane & 3;           // 0..3

    const int q0 = blockIdx.x * 128;
    const int h  = blockIdx.y;
    const int n  = blockIdx.z;
    const int kvh = h >> 1;
    const float slope = exp2f(-(float)(h + 1));

    // ---- stage Q [q][d] into Ps (tf32) ----
#pragma unroll
    for (int p = 0; p < 16; p++) {
        int f4 = tid + p * 128;          // 0..2047
        int qi = f4 >> 4;                // 0..127
        int d4 = f4 & 15;
        float4 a = *(const float4*)(g_q + (size_t)(n * SEQ + q0 + qi) * (NH * HD)
                                        + h * HD + d4 * 4);
        uint4 t = { f2tf(a.x), f2tf(a.y), f2tf(a.z), f2tf(a.w) };
        *(uint4*)&Ps[qi * LTT + d4 * 4] = t;
    }
    __syncthreads();

    const int r0 = wid * 32 + fr;
    uint32_t qf0[8][4], qf1[8][4];
#pragma unroll
    for (int ks = 0; ks < 8; ks++) {
        qf0[ks][0] = Ps[r0 * LTT + ks * 8 + fc];
        qf0[ks][1] = Ps[(r0 + 8) * LTT + ks * 8 + fc];
        qf0[ks][2] = Ps[r0 * LTT + ks * 8 + fc + 4];
        qf0[ks][3] = Ps[(r0 + 8) * LTT + ks * 8 + fc + 4];
        qf1[ks][0] = Ps[(r0 + 16) * LTT + ks * 8 + fc];
        qf1[ks][1] = Ps[(r0 + 24) * LTT + ks * 8 + fc];
        qf1[ks][2] = Ps[(r0 + 16) * LTT + ks * 8 + fc + 4];
        qf1[ks][3] = Ps[(r0 + 24) * LTT + ks * 8 + fc + 4];
    }

    float o0[8][4], o1[8][4];
#pragma unroll
    for (int nt = 0; nt < 8; nt++)
#pragma unroll
        for (int i = 0; i < 4; i++) { o0[nt][i] = 0.f; o1[nt][i] = 0.f; }
    float m00 = -INFINITY, m01 = -INFINITY, m10 = -INFINITY, m11 = -INFINITY;
    float l00 = 0.f, l01 = 0.f, l10 = 0.f, l11 = 0.f;

    const float gq0 = (float)(q0 + wid * 32 + fr);

    for (int kb = 0; kb < SEQ / 64; kb++) {
        __syncthreads();

        // ---- stage K (transposed, swizzled) and V (tf32) ----
#pragma unroll
        for (int p = 0; p < 8; p++) {
            int f4 = tid + p * 128;
            int ki = f4 >> 4;            // 0..63
            int d4 = f4 & 15;
            size_t gk = (size_t)(n * SEQ + kb * 64 + ki) * (NKV * HD) + kvh * HD + d4 * 4;
            float4 a = *(const float4*)(g_k + gk);
            int sc = ki ^ (d4 * 4);
            Kt[(d4 * 4 + 0) * LTK + sc] = f2tf(a.x);
            Kt[(d4 * 4 + 1) * LTK + sc] = f2tf(a.y);
            Kt[(d4 * 4 + 2) * LTK + sc] = f2tf(a.z);
            Kt[(d4 * 4 + 3) * LTK + sc] = f2tf(a.w);
            float4 b = *(const float4*)(g_v + gk);
            uint4 t = { f2tf(b.x), f2tf(b.y), f2tf(b.z), f2tf(b.w) };
            *(uint4*)&Vs[ki * LTK + d4 * 4] = t;
        }
        __syncthreads();

        // ---- S = Q @ K^T for both 16-row blocks, K frags loaded once ----
        float s0[8][4], s1[8][4];
#pragma unroll
        for (int nt = 0; nt < 8; nt++)
#pragma unroll
            for (int i = 0; i < 4; i++) { s0[nt][i] = 0.f; s1[nt][i] = 0.f; }

#pragma unroll
        for (int ks = 0; ks < 8; ks++) {
            uint32_t bf[8][2];
#pragma unroll
            for (int nt = 0; nt < 8; nt++) {
                int cswz = 8 * (nt ^ ks);
                bf[nt][0] = Kt[(ks * 8 + fc) * LTK + cswz + fr];
                bf[nt][1] = Kt[(ks * 8 + 4 + fc) * LTK + cswz + (fr ^ 4)];
            }
#pragma unroll
            for (int nt = 0; nt < 8; nt++) {
                mma_tf32(s0[nt], qf0[ks], bf[nt]);
                mma_tf32(s1[nt], qf1[ks], bf[nt]);
            }
        }

        // ---- ALiBi + scale ----
#pragma unroll
        for (int nt = 0; nt < 8; nt++) {
            float k0f = (float)(kb * 64 + nt * 8 + 2 * fc);
            float k1f = k0f + 1.f;
            s0[nt][0] = (s0[nt][0] - fabsf(gq0 - k0f) * slope) * 0.125f;
            s0[nt][1] = (s0[nt][1] - fabsf(gq0 - k1f) * slope) * 0.125f;
            s0[nt][2] = (s0[nt][2] - fabsf((gq0 + 8.f) - k0f) * slope) * 0.125f;
            s0[nt][3] = (s0[nt][3] - fabsf((gq0 + 8.f) - k1f) * slope) * 0.125f;
            s1[nt][0] = (s1[nt][0] - fabsf((gq0 + 16.f) - k0f) * slope) * 0.125f;
            s1[nt][1] = (s1[nt][1] - fabsf((gq0 + 16.f) - k1f) * slope) * 0.125f;
            s1[nt][2] = (s1[nt][2] - fabsf((gq0 + 24.f) - k0f) * slope) * 0.125f;
            s1[nt][3] = (s1[nt][3] - fabsf((gq0 + 24.f) - k1f) * slope) * 0.125f;
        }

        // ---- online softmax, block0 ----
        {
            float mt0 = -INFINITY, mt1 = -INFINITY;
#pragma unroll
            for (int nt = 0; nt < 8; nt++) {
                mt0 = fmaxf(mt0, fmaxf(s0[nt][0], s0[nt][1]));
                mt1 = fmaxf(mt1, fmaxf(s0[nt][2], s0[nt][3]));
            }
            mt0 = fmaxf(mt0, __shfl_xor_sync(0xffffffffu, mt0, 1));
            mt0 = fmaxf(mt0, __shfl_xor_sync(0xffffffffu, mt0, 2));
            mt1 = fmaxf(mt1, __shfl_xor_sync(0xffffffffu, mt1, 1));
            mt1 = fmaxf(mt1, __shfl_xor_sync(0xffffffffu, mt1, 2));
            float mn0 = fmaxf(m00, mt0), mn1 = fmaxf(m01, mt1);
            float c0 = __expf(m00 - mn0), c1 = __expf(m01 - mn1);
            m00 = mn0; m01 = mn1;
            float rs0 = 0.f, rs1 = 0.f;
#pragma unroll
            for (int nt = 0; nt < 8; nt++) {
                float p0 = __expf(s0[nt][0] - mn0);
                float p1 = __expf(s0[nt][1] - mn0);
                float p2 = __expf(s0[nt][2] - mn1);
                float p3 = __expf(s0[nt][3] - mn1);
                rs0 += p0 + p1; rs1 += p2 + p3;
                uint2 w0 = { f2tf(p0), f2tf(p1) };
                uint2 w1 = { f2tf(p2), f2tf(p3) };
                *(uint2*)&Ps[r0 * LTT + nt * 8 + 2 * fc]       = w0;
                *(uint2*)&Ps[(r0 + 8) * LTT + nt * 8 + 2 * fc] = w1;
            }
            rs0 += __shfl_xor_sync(0xffffffffu, rs0, 1);
            rs0 += __shfl_xor_sync(0xffffffffu, rs0, 2);
            rs1 += __shfl_xor_sync(0xffffffffu, rs1, 1);
            rs1 += __shfl_xor_sync(0xffffffffu, rs1, 2);
            l00 = l00 * c0 + rs0;
            l01 = l01 * c1 + rs1;
#pragma unroll
            for (int nt = 0; nt < 8; nt++) {
                o0[nt][0] *= c0; o0[nt][1] *= c0;
                o0[nt][2] *= c1; o0[nt][3] *= c1;
            }
        }
        // ---- online softmax, block1 ----
        {
            float mt0 = -INFINITY, mt1 = -INFINITY;
#pragma unroll
            for (int nt = 0; nt < 8; nt++) {
                mt0 = fmaxf(mt0, fmaxf(s1[nt][0], s1[nt][1]));
                mt1 = fmaxf(mt1, fmaxf(s1[nt][2], s1[nt][3]));
            }
            mt0 = fmaxf(mt0, __shfl_xor_sync(0xffffffffu, mt0, 1));
            mt0 = fmaxf(mt0, __shfl_xor_sync(0xffffffffu, mt0, 2));
            mt1 = fmaxf(mt1, __shfl_xor_sync(0xffffffffu, mt1, 1));
            mt1 = fmaxf(mt1, __shfl_xor_sync(0xffffffffu, mt1, 2));
            float mn0 = fmaxf(m10, mt0), mn1 = fmaxf(m11, mt1);
            float c0 = __expf(m10 - mn0), c1 = __expf(m11 - mn1);
            m10 = mn0; m11 = mn1;
            float rs0 = 0.f, rs1 = 0.f;
#pragma unroll
            for (int nt = 0; nt < 8; nt++) {
                float p0 = __expf(s1[nt][0] - mn0);
                float p1 = __expf(s1[nt][1] - mn0);
                float p2 = __expf(s1[nt][2] - mn1);
                float p3 = __expf(s1[nt][3] - mn1);
                rs0 += p0 + p1; rs1 += p2 + p3;
                uint2 w0 = { f2tf(p0), f2tf(p1) };
                uint2 w1 = { f2tf(p2), f2tf(p3) };
                *(uint2*)&Ps[(r0 + 16) * LTT + nt * 8 + 2 * fc] = w0;
                *(uint2*)&Ps[(r0 + 24) * LTT + nt * 8 + 2 * fc] = w1;
            }
            rs0 += __shfl_xor_sync(0xffffffffu, rs0, 1);
            rs0 += __shfl_xor_sync(0xffffffffu, rs0, 2);
            rs1 += __shfl_xor_sync(0xffffffffu, rs1, 1);
            rs1 += __shfl_xor_sync(0xffffffffu, rs1, 2);
            l10 = l10 * c0 + rs0;
            l11 = l11 * c1 + rs1;
#pragma unroll
            for (int nt = 0; nt < 8; nt++) {
                o1[nt][0] *= c0; o1[nt][1] *= c0;
                o1[nt][2] *= c1; o1[nt][3] *= c1;
            }
        }
        __syncwarp();

        // ---- O += P @ V ----
#pragma unroll
        for (int ks = 0; ks < 8; ks++) {
            uint32_t af0[4], af1[4], bf[8][2];
            af0[0] = Ps[r0 * LTT + ks * 8 + fc];
            af0[1] = Ps[(r0 + 8) * LTT + ks * 8 + fc];
            af0[2] = Ps[r0 * LTT + ks * 8 + fc + 4];
            af0[3] = Ps[(r0 + 8) * LTT + ks * 8 + fc + 4];
            af1[0] = Ps[(r0 + 16) * LTT + ks * 8 + fc];
            af1[1] = Ps[(r0 + 24) * LTT + ks * 8 + fc];
            af1[2] = Ps[(r0 + 16) * LTT + ks * 8 + fc + 4];
            af1[3] = Ps[(r0 + 24) * LTT + ks * 8 + fc + 4];
#pragma unroll
            for (int nt = 0; nt < 8; nt++) {
                bf[nt][0] = Vs[(ks * 8 + fc) * LTK + nt * 8 + fr];
                bf[nt][1] = Vs[(ks * 8 + fc + 4) * LTK + nt * 8 + fr];
            }
#pragma unroll
            for (int nt = 0; nt < 8; nt++) {
                mma_tf32(o0[nt], af0, bf[nt]);
                mma_tf32(o1[nt], af1, bf[nt]);
            }
        }
    }

    // ---- normalize + write ----
    {
        float i00 = 1.f / l00, i01 = 1.f / l01, i10 = 1.f / l10, i11 = 1.f / l11;
        const int qr = q0 + wid * 32 + fr;
        float* b0 = g_attn + (size_t)(n * SEQ + qr) * (NH * HD) + h * HD;
        float* b1 = g_attn + (size_t)(n * SEQ + qr + 8) * (NH * HD) + h * HD;
        float* b2 = g_attn + (size_t)(n * SEQ + qr + 16) * (NH * HD) + h * HD;
        float* b3 = g_attn + (size_t)(n * SEQ + qr + 24) * (NH * HD) + h * HD;
#pragma unroll
        for (int nt = 0; nt < 8; nt++) {
            float2 w0 = { o0[nt][0] * i00, o0[nt][1] * i00 };
            float2 w1 = { o0[nt][2] * i01, o0[nt][3] * i01 };
            float2 w2 = { o1[nt][0] * i10, o1[nt][1] * i10 };
            float2 w3 = { o1[nt][2] * i11, o1[nt][3] * i11 };
            *(float2*)(b0 + nt * 8 + 2 * fc) = w0;
            *(float2*)(b1 + nt * 8 + 2 * fc) = w1;
            *(float2*)(b2 + nt * 8 + 2 * fc) = w2;
            *(float2*)(b3 + nt * 8 + 2 * fc) = w3;
        }
    }
}

// =====================================================================
// launch
// =====================================================================
extern "C" void kernel_launch(void* const* d_in, const int* in_sizes, int n_in,
                              void* d_out, int out_size)
{
    const float* x  = (const float*)d_in[0];
    const float* Wq = (const float*)d_in[1];
    const float* Wk = (const float*)d_in[2];
    const float* Wv = (const float*)d_in[3];
    const float* Wo = (const float*)d_in[4];
    const float* bo = (const float*)d_in[5];
    float* out = (float*)d_out;

    float *qp, *kp, *vp, *ap;
    cudaGetSymbolAddress((void**)&qp, g_q);
    cudaGetSymbolAddress((void**)&kp, g_k);
    cudaGetSymbolAddress((void**)&vp, g_v);
    cudaGetSymbolAddress((void**)&ap, g_attn);

    // fused QKV projections (mma.sync tf32, one launch)
    gemm_qkv<<<dim3(16, MROWS / 128), 256>>>(x, Wq, Wk, Wv, qp, kp, vp);

    // attention (mma.sync tf32 flash, conflict-free strides)
    int smemf = (64 * LTK * 2 + 128 * LTT) * (int)sizeof(uint32_t);   // 71680
    cudaFuncSetAttribute(flash_mma, cudaFuncAttributeMaxDynamicSharedMemorySize, smemf);
    flash_mma<<<dim3(SEQ / 128, NH, NB), 128, smemf>>>();

    // output projection + bias (mma.sync tf32)
    gemm_mma<<<dim3(EMB / 128, MROWS / 128), 256>>>(ap, Wo, bo, out,
                                                    MROWS, EMB, EMB);
}

// round 7
// speedup vs baseline: 3.3133x; 1.0229x over previous
#include <cuda_runtime.h>
#include <math.h>
#include <stdint.h>

#define NB   2
#define SEQ  2048
#define EMB  1024
#define NH   16
#define NKV  8
#define HD   64
#define MROWS (NB*SEQ)   // 4096

// ---------------- scratch (no allocations allowed) ----------------
__device__ float g_q[(size_t)MROWS * NH * HD];    // 16 MB
__device__ float g_k[(size_t)MROWS * NKV * HD];   // 8 MB
__device__ float g_v[(size_t)MROWS * NKV * HD];   // 8 MB
__device__ float g_attn[(size_t)MROWS * NH * HD]; // 16 MB

// =====================================================================
// helpers
// =====================================================================
__device__ __forceinline__ uint32_t f2tf(float f) {
    uint32_t u;
    asm("cvt.rna.tf32.f32 %0, %1;" : "=r"(u) : "f"(f));
    return u;
}
__device__ __forceinline__ void mma_tf32(float* d, const uint32_t* a, const uint32_t* b) {
    asm volatile(
        "mma.sync.aligned.m16n8k8.row.col.f32.tf32.tf32.f32 "
        "{%0,%1,%2,%3}, {%4,%5,%6,%7}, {%8,%9}, {%0,%1,%2,%3};"
        : "+f"(d[0]), "+f"(d[1]), "+f"(d[2]), "+f"(d[3])
        : "r"(a[0]), "r"(a[1]), "r"(a[2]), "r"(a[3]), "r"(b[0]), "r"(b[1]));
}

// =====================================================================
// mma.sync tf32 GEMM body: C[M,N] = A[M,K] @ B[N,K]^T (+ bias[N])
// =====================================================================
#define LT 36

__device__ __forceinline__
void gemm_body(const float* __restrict__ A, const float* __restrict__ B,
               const float* __restrict__ bias, float* __restrict__ C,
               int N, int K, int m0, int n0)
{
    __shared__ uint32_t As[128][LT];
    __shared__ uint32_t Bs[128][LT];

    const int tid  = threadIdx.x;
    const int lane = tid & 31;
    const int wid  = tid >> 5;
    const int wm   = wid >> 2;
    const int wn   = wid & 3;

    const int srow = tid >> 3;
    const int sc4  = (tid & 7) * 4;

    float acc[4][4][4];
#pragma unroll
    for (int mt = 0; mt < 4; mt++)
#pragma unroll
        for (int nt = 0; nt < 4; nt++)
#pragma unroll
            for (int i = 0; i < 4; i++) acc[mt][nt][i] = 0.f;

    float4 ra[4], rb[4];

#pragma unroll
    for (int p = 0; p < 4; p++) {
        int row = srow + p * 32;
        ra[p] = *(const float4*)(A + (size_t)(m0 + row) * K + sc4);
        rb[p] = *(const float4*)(B + (size_t)(n0 + row) * K + sc4);
    }
#pragma unroll
    for (int p = 0; p < 4; p++) {
        int row = srow + p * 32;
        uint4 ta = { f2tf(ra[p].x), f2tf(ra[p].y), f2tf(ra[p].z), f2tf(ra[p].w) };
        *(uint4*)&As[row][sc4] = ta;
        uint4 tb = { f2tf(rb[p].x), f2tf(rb[p].y), f2tf(rb[p].z), f2tf(rb[p].w) };
        *(uint4*)&Bs[row][sc4] = tb;
    }
    __syncthreads();

    const int NC = K / 32;
    const int fr = lane >> 2;
    const int fc = lane & 3;

    for (int ch = 0; ch < NC; ch++) {
        if (ch + 1 < NC) {
            int k0 = (ch + 1) * 32;
#pragma unroll
            for (int p = 0; p < 4; p++) {
                int row = srow + p * 32;
                ra[p] = *(const float4*)(A + (size_t)(m0 + row) * K + k0 + sc4);
                rb[p] = *(const float4*)(B + (size_t)(n0 + row) * K + k0 + sc4);
            }
        }

#pragma unroll
        for (int ks = 0; ks < 4; ks++) {
            uint32_t af[4][4], bf[4][2];
#pragma unroll
            for (int mt = 0; mt < 4; mt++) {
                int m = wm * 64 + mt * 16 + fr;
                af[mt][0] = As[m][ks * 8 + fc];
                af[mt][1] = As[m + 8][ks * 8 + fc];
                af[mt][2] = As[m][ks * 8 + fc + 4];
                af[mt][3] = As[m + 8][ks * 8 + fc + 4];
            }
#pragma unroll
            for (int nt = 0; nt < 4; nt++) {
                int n = wn * 32 + nt * 8 + fr;
                bf[nt][0] = Bs[n][ks * 8 + fc];
                bf[nt][1] = Bs[n][ks * 8 + fc + 4];
            }
#pragma unroll
            for (int mt = 0; mt < 4; mt++)
#pragma unroll
                for (int nt = 0; nt < 4; nt++)
                    mma_tf32(acc[mt][nt], af[mt], bf[nt]);
        }
        __syncthreads();

        if (ch + 1 < NC) {
#pragma unroll
            for (int p = 0; p < 4; p++) {
                int row = srow + p * 32;
                uint4 ta = { f2tf(ra[p].x), f2tf(ra[p].y), f2tf(ra[p].z), f2tf(ra[p].w) };
                *(uint4*)&As[row][sc4] = ta;
                uint4 tb = { f2tf(rb[p].x), f2tf(rb[p].y), f2tf(rb[p].z), f2tf(rb[p].w) };
                *(uint4*)&Bs[row][sc4] = tb;
            }
            __syncthreads();
        }
    }

    const int c2 = (lane & 3) * 2;
#pragma unroll
    for (int mt = 0; mt < 4; mt++) {
        int m = m0 + wm * 64 + mt * 16 + fr;
#pragma unroll
        for (int nt = 0; nt < 4; nt++) {
            int n = n0 + wn * 32 + nt * 8 + c2;
            float b0 = 0.f, b1 = 0.f;
            if (bias) { b0 = bias[n]; b1 = bias[n + 1]; }
            float2 v0 = { acc[mt][nt][0] + b0, acc[mt][nt][1] + b1 };
            float2 v1 = { acc[mt][nt][2] + b0, acc[mt][nt][3] + b1 };
            *(float2*)(C + (size_t)m * N + n)       = v0;
            *(float2*)(C + (size_t)(m + 8) * N + n) = v1;
        }
    }
}

// fused QKV: blockIdx.x 0..7 -> Q, 8..11 -> K, 12..15 -> V
__global__ __launch_bounds__(256)
void gemm_qkv(const float* __restrict__ x,
              const float* __restrict__ Wq, const float* __restrict__ Wk,
              const float* __restrict__ Wv,
              float* __restrict__ q, float* __restrict__ k, float* __restrict__ v)
{
    const int bx = blockIdx.x;
    const int m0 = blockIdx.y * 128;
    if (bx < 8)       gemm_body(x, Wq, nullptr, q, NH * HD,  EMB, m0, bx * 128);
    else if (bx < 12) gemm_body(x, Wk, nullptr, k, NKV * HD, EMB, m0, (bx - 8) * 128);
    else              gemm_body(x, Wv, nullptr, v, NKV * HD, EMB, m0, (bx - 12) * 128);
}

__global__ __launch_bounds__(256)
void gemm_mma(const float* __restrict__ A, const float* __restrict__ B,
              const float* __restrict__ bias, float* __restrict__ C,
              int M, int N, int K)
{
    gemm_body(A, B, bias, C, N, K, blockIdx.y * 128, blockIdx.x * 128);
}

// =====================================================================
// Flash attention on tensor cores (mma.sync tf32), v4:
// 4 warps x 32 q-rows (BQ=128), BK=64.
// Ks: [key][d] stride 68 (b-frag bank = 4fr+fc, conflict-free; fast staging)
// Vs: [key][d] stride 72 (b-frag bank = 8fc+fr, conflict-free)
// Ps: [q][*]  stride 68 (Q staging, then P)
// exp2-domain softmax: Q pre-scaled by 0.125*log2e, slope folded.
// =====================================================================
#define LTK 68   // Ks stride
#define LTV 72   // Vs stride
#define LTT 68   // Ps stride
#define QSC 0.18033688011112042f   // 0.125 * log2(e)

__global__ __launch_bounds__(128, 2)
void flash_mma()
{
    extern __shared__ uint32_t smf[];
    uint32_t* Ks = smf;                  // [64][68] k-major
    uint32_t* Vs = Ks + 64 * LTK;        // [64][72] k-major
    uint32_t* Ps = Vs + 64 * LTV;        // [128][68] q-major

    const int tid  = threadIdx.x;
    const int lane = tid & 31;
    const int wid  = tid >> 5;           // 0..3 : q-rows [wid*32, wid*32+32)
    const int fr   = lane >> 2;          // 0..7
    const int fc   = lane & 3;           // 0..3

    const int q0 = blockIdx.x * 128;
    const int h  = blockIdx.y;
    const int n  = blockIdx.z;
    const int kvh = h >> 1;
    const float slope2 = exp2f(-(float)(h + 1)) * QSC;   // alibi slope in exp2 domain

    // ---- stage Q [q][d] into Ps (pre-scaled, tf32) ----
#pragma unroll
    for (int p = 0; p < 16; p++) {
        int f4 = tid + p * 128;          // 0..2047
        int qi = f4 >> 4;                // 0..127
        int d4 = f4 & 15;
        float4 a = *(const float4*)(g_q + (size_t)(n * SEQ + q0 + qi) * (NH * HD)
                                        + h * HD + d4 * 4);
        uint4 t = { f2tf(a.x * QSC), f2tf(a.y * QSC), f2tf(a.z * QSC), f2tf(a.w * QSC) };
        *(uint4*)&Ps[qi * LTT + d4 * 4] = t;
    }
    __syncthreads();

    const int r0 = wid * 32 + fr;
    uint32_t qf0[8][4], qf1[8][4];
#pragma unroll
    for (int ks = 0; ks < 8; ks++) {
        qf0[ks][0] = Ps[r0 * LTT + ks * 8 + fc];
        qf0[ks][1] = Ps[(r0 + 8) * LTT + ks * 8 + fc];
        qf0[ks][2] = Ps[r0 * LTT + ks * 8 + fc + 4];
        qf0[ks][3] = Ps[(r0 + 8) * LTT + ks * 8 + fc + 4];
        qf1[ks][0] = Ps[(r0 + 16) * LTT + ks * 8 + fc];
        qf1[ks][1] = Ps[(r0 + 24) * LTT + ks * 8 + fc];
        qf1[ks][2] = Ps[(r0 + 16) * LTT + ks * 8 + fc + 4];
        qf1[ks][3] = Ps[(r0 + 24) * LTT + ks * 8 + fc + 4];
    }

    float o0[8][4], o1[8][4];
#pragma unroll
    for (int nt = 0; nt < 8; nt++)
#pragma unroll
        for (int i = 0; i < 4; i++) { o0[nt][i] = 0.f; o1[nt][i] = 0.f; }
    float m00 = -INFINITY, m01 = -INFINITY, m10 = -INFINITY, m11 = -INFINITY;
    float l00 = 0.f, l01 = 0.f, l10 = 0.f, l11 = 0.f;

    const float gq0 = (float)(q0 + wid * 32 + fr);

    for (int kb = 0; kb < SEQ / 64; kb++) {
        __syncthreads();

        // ---- stage K and V (k-major, tf32) ----
#pragma unroll
        for (int p = 0; p < 8; p++) {
            int f4 = tid + p * 128;
            int ki = f4 >> 4;            // 0..63
            int d4 = f4 & 15;
            size_t gk = (size_t)(n * SEQ + kb * 64 + ki) * (NKV * HD) + kvh * HD + d4 * 4;
            float4 a = *(const float4*)(g_k + gk);
            uint4 ta = { f2tf(a.x), f2tf(a.y), f2tf(a.z), f2tf(a.w) };
            *(uint4*)&Ks[ki * LTK + d4 * 4] = ta;
            float4 b = *(const float4*)(g_v + gk);
            uint4 tb = { f2tf(b.x), f2tf(b.y), f2tf(b.z), f2tf(b.w) };
            *(uint4*)&Vs[ki * LTV + d4 * 4] = tb;
        }
        __syncthreads();

        // ---- S = Q @ K^T for both 16-row blocks, K frags loaded once ----
        float s0[8][4], s1[8][4];
#pragma unroll
        for (int nt = 0; nt < 8; nt++)
#pragma unroll
            for (int i = 0; i < 4; i++) { s0[nt][i] = 0.f; s1[nt][i] = 0.f; }

#pragma unroll
        for (int ks = 0; ks < 8; ks++) {
            uint32_t bf[8][2];
#pragma unroll
            for (int nt = 0; nt < 8; nt++) {
                bf[nt][0] = Ks[(nt * 8 + fr) * LTK + ks * 8 + fc];
                bf[nt][1] = Ks[(nt * 8 + fr) * LTK + ks * 8 + fc + 4];
            }
#pragma unroll
            for (int nt = 0; nt < 8; nt++) {
                mma_tf32(s0[nt], qf0[ks], bf[nt]);
                mma_tf32(s1[nt], qf1[ks], bf[nt]);
            }
        }

        // ---- ALiBi (exp2 domain, single FFMA each) ----
#pragma unroll
        for (int nt = 0; nt < 8; nt++) {
            float k0f = (float)(kb * 64 + nt * 8 + 2 * fc);
            float k1f = k0f + 1.f;
            s0[nt][0] = fmaf(-slope2, fabsf(gq0 - k0f), s0[nt][0]);
            s0[nt][1] = fmaf(-slope2, fabsf(gq0 - k1f), s0[nt][1]);
            s0[nt][2] = fmaf(-slope2, fabsf((gq0 + 8.f) - k0f), s0[nt][2]);
            s0[nt][3] = fmaf(-slope2, fabsf((gq0 + 8.f) - k1f), s0[nt][3]);
            s1[nt][0] = fmaf(-slope2, fabsf((gq0 + 16.f) - k0f), s1[nt][0]);
            s1[nt][1] = fmaf(-slope2, fabsf((gq0 + 16.f) - k1f), s1[nt][1]);
            s1[nt][2] = fmaf(-slope2, fabsf((gq0 + 24.f) - k0f), s1[nt][2]);
            s1[nt][3] = fmaf(-slope2, fabsf((gq0 + 24.f) - k1f), s1[nt][3]);
        }

        // ---- online softmax (exp2 domain), block0 ----
        {
            float mt0 = -INFINITY, mt1 = -INFINITY;
#pragma unroll
            for (int nt = 0; nt < 8; nt++) {
                mt0 = fmaxf(mt0, fmaxf(s0[nt][0], s0[nt][1]));
                mt1 = fmaxf(mt1, fmaxf(s0[nt][2], s0[nt][3]));
            }
            mt0 = fmaxf(mt0, __shfl_xor_sync(0xffffffffu, mt0, 1));
            mt0 = fmaxf(mt0, __shfl_xor_sync(0xffffffffu, mt0, 2));
            mt1 = fmaxf(mt1, __shfl_xor_sync(0xffffffffu, mt1, 1));
            mt1 = fmaxf(mt1, __shfl_xor_sync(0xffffffffu, mt1, 2));
            float mn0 = fmaxf(m00, mt0), mn1 = fmaxf(m01, mt1);
            float c0 = exp2f(m00 - mn0), c1 = exp2f(m01 - mn1);
            m00 = mn0; m01 = mn1;
            float rs0 = 0.f, rs1 = 0.f;
#pragma unroll
            for (int nt = 0; nt < 8; nt++) {
                float p0 = exp2f(s0[nt][0] - mn0);
                float p1 = exp2f(s0[nt][1] - mn0);
                float p2 = exp2f(s0[nt][2] - mn1);
                float p3 = exp2f(s0[nt][3] - mn1);
                rs0 += p0 + p1; rs1 += p2 + p3;
                uint2 w0 = { f2tf(p0), f2tf(p1) };
                uint2 w1 = { f2tf(p2), f2tf(p3) };
                *(uint2*)&Ps[r0 * LTT + nt * 8 + 2 * fc]       = w0;
                *(uint2*)&Ps[(r0 + 8) * LTT + nt * 8 + 2 * fc] = w1;
            }
            rs0 += __shfl_xor_sync(0xffffffffu, rs0, 1);
            rs0 += __shfl_xor_sync(0xffffffffu, rs0, 2);
            rs1 += __shfl_xor_sync(0xffffffffu, rs1, 1);
            rs1 += __shfl_xor_sync(0xffffffffu, rs1, 2);
            l00 = l00 * c0 + rs0;
            l01 = l01 * c1 + rs1;
#pragma unroll
            for (int nt = 0; nt < 8; nt++) {
                o0[nt][0] *= c0; o0[nt][1] *= c0;
                o0[nt][2] *= c1; o0[nt][3] *= c1;
            }
        }
        // ---- online softmax, block1 ----
        {
            float mt0 = -INFINITY, mt1 = -INFINITY;
#pragma unroll
            for (int nt = 0; nt < 8; nt++) {
                mt0 = fmaxf(mt0, fmaxf(s1[nt][0], s1[nt][1]));
                mt1 = fmaxf(mt1, fmaxf(s1[nt][2], s1[nt][3]));
            }
            mt0 = fmaxf(mt0, __shfl_xor_sync(0xffffffffu, mt0, 1));
            mt0 = fmaxf(mt0, __shfl_xor_sync(0xffffffffu, mt0, 2));
            mt1 = fmaxf(mt1, __shfl_xor_sync(0xffffffffu, mt1, 1));
            mt1 = fmaxf(mt1, __shfl_xor_sync(0xffffffffu, mt1, 2));
            float mn0 = fmaxf(m10, mt0), mn1 = fmaxf(m11, mt1);
            float c0 = exp2f(m10 - mn0), c1 = exp2f(m11 - mn1);
            m10 = mn0; m11 = mn1;
            float rs0 = 0.f, rs1 = 0.f;
#pragma unroll
            for (int nt = 0; nt < 8; nt++) {
                float p0 = exp2f(s1[nt][0] - mn0);
                float p1 = exp2f(s1[nt][1] - mn0);
                float p2 = exp2f(s1[nt][2] - mn1);
                float p3 = exp2f(s1[nt][3] - mn1);
                rs0 += p0 + p1; rs1 += p2 + p3;
                uint2 w0 = { f2tf(p0), f2tf(p1) };
                uint2 w1 = { f2tf(p2), f2tf(p3) };
                *(uint2*)&Ps[(r0 + 16) * LTT + nt * 8 + 2 * fc] = w0;
                *(uint2*)&Ps[(r0 + 24) * LTT + nt * 8 + 2 * fc] = w1;
            }
            rs0 += __shfl_xor_sync(0xffffffffu, rs0, 1);
            rs0 += __shfl_xor_sync(0xffffffffu, rs0, 2);
            rs1 += __shfl_xor_sync(0xffffffffu, rs1, 1);
            rs1 += __shfl_xor_sync(0xffffffffu, rs1, 2);
            l10 = l10 * c0 + rs0;
            l11 = l11 * c1 + rs1;
#pragma unroll
            for (int nt = 0; nt < 8; nt++) {
                o1[nt][0] *= c0; o1[nt][1] *= c0;
                o1[nt][2] *= c1; o1[nt][3] *= c1;
            }
        }
        __syncwarp();

        // ---- O += P @ V ----
#pragma unroll
        for (int ks = 0; ks < 8; ks++) {
            uint32_t af0[4], af1[4], bf[8][2];
            af0[0] = Ps[r0 * LTT + ks * 8 + fc];
            af0[1] = Ps[(r0 + 8) * LTT + ks * 8 + fc];
            af0[2] = Ps[r0 * LTT + ks * 8 + fc + 4];
            af0[3] = Ps[(r0 + 8) * LTT + ks * 8 + fc + 4];
            af1[0] = Ps[(r0 + 16) * LTT + ks * 8 + fc];
            af1[1] = Ps[(r0 + 24) * LTT + ks * 8 + fc];
            af1[2] = Ps[(r0 + 16) * LTT + ks * 8 + fc + 4];
            af1[3] = Ps[(r0 + 24) * LTT + ks * 8 + fc + 4];
#pragma unroll
            for (int nt = 0; nt < 8; nt++) {
                bf[nt][0] = Vs[(ks * 8 + fc) * LTV + nt * 8 + fr];
                bf[nt][1] = Vs[(ks * 8 + fc + 4) * LTV + nt * 8 + fr];
            }
#pragma unroll
            for (int nt = 0; nt < 8; nt++) {
                mma_tf32(o0[nt], af0, bf[nt]);
                mma_tf32(o1[nt], af1, bf[nt]);
            }
        }
    }

    // ---- normalize + write ----
    {
        float i00 = 1.f / l00, i01 = 1.f / l01, i10 = 1.f / l10, i11 = 1.f / l11;
        const int qr = q0 + wid * 32 + fr;
        float* b0 = g_attn + (size_t)(n * SEQ + qr) * (NH * HD) + h * HD;
        float* b1 = g_attn + (size_t)(n * SEQ + qr + 8) * (NH * HD) + h * HD;
        float* b2 = g_attn + (size_t)(n * SEQ + qr + 16) * (NH * HD) + h * HD;
        float* b3 = g_attn + (size_t)(n * SEQ + qr + 24) * (NH * HD) + h * HD;
#pragma unroll
        for (int nt = 0; nt < 8; nt++) {
            float2 w0 = { o0[nt][0] * i00, o0[nt][1] * i00 };
            float2 w1 = { o0[nt][2] * i01, o0[nt][3] * i01 };
            float2 w2 = { o1[nt][0] * i10, o1[nt][1] * i10 };
            float2 w3 = { o1[nt][2] * i11, o1[nt][3] * i11 };
            *(float2*)(b0 + nt * 8 + 2 * fc) = w0;
            *(float2*)(b1 + nt * 8 + 2 * fc) = w1;
            *(float2*)(b2 + nt * 8 + 2 * fc) = w2;
            *(float2*)(b3 + nt * 8 + 2 * fc) = w3;
        }
    }
}

// =====================================================================
// launch
// =====================================================================
extern "C" void kernel_launch(void* const* d_in, const int* in_sizes, int n_in,
                              void* d_out, int out_size)
{
    const float* x  = (const float*)d_in[0];
    const float* Wq = (const float*)d_in[1];
    const float* Wk = (const float*)d_in[2];
    const float* Wv = (const float*)d_in[3];
    const float* Wo = (const float*)d_in[4];
    const float* bo = (const float*)d_in[5];
    float* out = (float*)d_out;

    float *qp, *kp, *vp, *ap;
    cudaGetSymbolAddress((void**)&qp, g_q);
    cudaGetSymbolAddress((void**)&kp, g_k);
    cudaGetSymbolAddress((void**)&vp, g_v);
    cudaGetSymbolAddress((void**)&ap, g_attn);

    // fused QKV projections (mma.sync tf32, one launch)
    gemm_qkv<<<dim3(16, MROWS / 128), 256>>>(x, Wq, Wk, Wv, qp, kp, vp);

    // attention (mma.sync tf32 flash)
    int smemf = (64 * LTK + 64 * LTV + 128 * LTT) * (int)sizeof(uint32_t);  // 70656
    cudaFuncSetAttribute(flash_mma, cudaFuncAttributeMaxDynamicSharedMemorySize, smemf);
    flash_mma<<<dim3(SEQ / 128, NH, NB), 128, smemf>>>();

    // output projection + bias (mma.sync tf32)
    gemm_mma<<<dim3(EMB / 128, MROWS / 128), 256>>>(ap, Wo, bo, out,
                                                    MROWS, EMB, EMB);
}